// round 1
// baseline (speedup 1.0000x reference)
#include <cuda_runtime.h>
#include <math.h>

// Problem constants
#define TKN   200704      // B*H*W tokens
#define CCH   96
#define NHD   3
#define HDIM  32
#define NWIN  64          // windows per image
#define NTOK  49          // tokens per window
#define BIMG  64
#define HIDD  384
#define QSCALE 0.17677669529663688f   // 32^-0.5

// Scratch (allocation-free rule: __device__ globals)
__device__ float g_buf1[200704 * 384];   // qkv [T,288] then h2 [T,384]
__device__ float g_buf2[200704 * 96];    // hw  [T,96]  then attn_out then ln2

// ---------------------------------------------------------------------------
// LN kernel: one warp per token. shifted=1: output row is window-layout token,
// source row computed via cyclic shift + window partition mapping.
// ---------------------------------------------------------------------------
__global__ void ln_kernel(const float* __restrict__ x, const float* __restrict__ g,
                          const float* __restrict__ b, float* __restrict__ out,
                          int shifted) {
    int warp = (blockIdx.x * blockDim.x + threadIdx.x) >> 5;
    int lane = threadIdx.x & 31;
    if (warp >= TKN) return;
    int src = warp;
    if (shifted) {
        int bi  = warp / (NWIN * NTOK);
        int rem = warp % (NWIN * NTOK);
        int w   = rem / NTOK, n = rem % NTOK;
        int wh = w >> 3, ww = w & 7;
        int r = n / 7, cc = n % 7;
        int sh = wh * 7 + r + 3;  if (sh >= 56) sh -= 56;
        int sw = ww * 7 + cc + 3; if (sw >= 56) sw -= 56;
        src = bi * 3136 + sh * 56 + sw;
    }
    const float* xr = x + (size_t)src * CCH;
    float v0 = xr[lane], v1 = xr[lane + 32], v2 = xr[lane + 64];
    float s  = v0 + v1 + v2;
    float s2 = v0 * v0 + v1 * v1 + v2 * v2;
    #pragma unroll
    for (int o = 16; o; o >>= 1) {
        s  += __shfl_xor_sync(0xffffffffu, s,  o);
        s2 += __shfl_xor_sync(0xffffffffu, s2, o);
    }
    float mean = s * (1.0f / 96.0f);
    float var  = s2 * (1.0f / 96.0f) - mean * mean;
    float rs   = rsqrtf(var + 1e-5f);
    float* orow = out + (size_t)warp * CCH;
    orow[lane]      = (v0 - mean) * rs * g[lane]      + b[lane];
    orow[lane + 32] = (v1 - mean) * rs * g[lane + 32] + b[lane + 32];
    orow[lane + 64] = (v2 - mean) * rs * g[lane + 64] + b[lane + 64];
}

// ---------------------------------------------------------------------------
// Tiled GEMM: C[M,N] = A[M,K] @ W[N,K]^T + bias, with per-mode epilogue.
// BM=64, BN=96, BK=48.  256 threads, each computes 4x6.
// MODE 0: qkv  (scale q columns, out stride 288)
// MODE 1: proj (window-reverse + unshift scatter, + residual x, out stride 96)
// MODE 2: fc1  (exact GELU, out stride 384)
// MODE 3: fc2  (accumulate into out, out stride 96)
// ---------------------------------------------------------------------------
template <int MODE>
__global__ void gemm_kernel(const float* __restrict__ A, const float* __restrict__ W,
                            const float* __restrict__ bias, float* __restrict__ out,
                            const float* __restrict__ resid, int K) {
    __shared__ float As[64 * 49];
    __shared__ float Bs[96 * 49];
    const int tid = threadIdx.x;
    const int tx = tid & 15, ty = tid >> 4;
    const int row0 = blockIdx.x * 64;
    const int col0 = blockIdx.y * 96;

    float acc[4][6];
    #pragma unroll
    for (int i = 0; i < 4; i++)
        #pragma unroll
        for (int j = 0; j < 6; j++) acc[i][j] = 0.0f;

    for (int kc = 0; kc < K; kc += 48) {
        for (int i = tid; i < 64 * 48; i += 256) {
            int r = i / 48, c = i % 48;
            As[r * 49 + c] = A[(size_t)(row0 + r) * K + kc + c];
        }
        for (int i = tid; i < 96 * 48; i += 256) {
            int r = i / 48, c = i % 48;
            Bs[r * 49 + c] = W[(size_t)(col0 + r) * K + kc + c];
        }
        __syncthreads();
        #pragma unroll 8
        for (int k = 0; k < 48; k++) {
            float a[4], bb[6];
            #pragma unroll
            for (int i = 0; i < 4; i++) a[i] = As[(ty * 4 + i) * 49 + k];
            #pragma unroll
            for (int j = 0; j < 6; j++) bb[j] = Bs[(tx * 6 + j) * 49 + k];
            #pragma unroll
            for (int i = 0; i < 4; i++)
                #pragma unroll
                for (int j = 0; j < 6; j++)
                    acc[i][j] = fmaf(a[i], bb[j], acc[i][j]);
        }
        __syncthreads();
    }

    #pragma unroll
    for (int i = 0; i < 4; i++) {
        int row = row0 + ty * 4 + i;
        int dst = row;
        if (MODE == 1) {
            int bi  = row / 3136;
            int rem = row % 3136;
            int w = rem / 49, n = rem % 49;
            int wh = w >> 3, ww = w & 7;
            int r7 = n / 7, c7 = n % 7;
            int hh = wh * 7 + r7 + 3; if (hh >= 56) hh -= 56;
            int zz = ww * 7 + c7 + 3; if (zz >= 56) zz -= 56;
            dst = bi * 3136 + hh * 56 + zz;
        }
        #pragma unroll
        for (int j = 0; j < 6; j++) {
            int col = col0 + tx * 6 + j;
            float v = acc[i][j] + bias[col];
            if (MODE == 0) {
                if (col < 96) v *= QSCALE;          // q pre-scaled
                out[(size_t)row * 288 + col] = v;
            } else if (MODE == 1) {
                size_t o = (size_t)dst * 96 + col;
                out[o] = resid[o] + v;
            } else if (MODE == 2) {
                out[(size_t)row * 384 + col] =
                    0.5f * v * (1.0f + erff(v * 0.70710678118654752f));
            } else {
                out[(size_t)row * 96 + col] += v;
            }
        }
    }
}

// ---------------------------------------------------------------------------
// Windowed attention: one block per (batch-window). 160 threads, thread=(h,i).
// K/V + rpb table in smem, shift mask & rel-pos index computed arithmetically.
// ---------------------------------------------------------------------------
__global__ void attn_kernel(const float* __restrict__ qkv,
                            const float* __restrict__ rpb,
                            float* __restrict__ out) {
    __shared__ float Ks[3 * 49 * 32];
    __shared__ float Vs[3 * 49 * 32];
    __shared__ float rpbs[169 * 3];
    __shared__ int   labs[49];

    const int wb = blockIdx.x;       // b*64 + window
    const int t0 = wb * 49;
    const int tid = threadIdx.x;

    for (int i = tid; i < 49 * 96; i += blockDim.x) {
        int r = i / 96, c = i % 96;
        int h = c >> 5, d = c & 31;
        Ks[(h * 49 + r) * 32 + d] = qkv[(size_t)(t0 + r) * 288 + 96  + c];
        Vs[(h * 49 + r) * 32 + d] = qkv[(size_t)(t0 + r) * 288 + 192 + c];
    }
    for (int i = tid; i < 169 * 3; i += blockDim.x) rpbs[i] = rpb[i];

    const int w  = wb & 63;
    const int wh = w >> 3, ww = w & 7;
    if (tid < 49) {
        int r = tid / 7, cc = tid % 7;
        int hh = wh * 7 + r, zz = ww * 7 + cc;
        int rh = (hh < 49) ? 0 : ((hh < 53) ? 1 : 2);
        int rw = (zz < 49) ? 0 : ((zz < 53) ? 1 : 2);
        labs[tid] = rh * 3 + rw;
    }
    __syncthreads();
    if (tid >= 147) return;

    const int h = tid / 49, i = tid % 49;
    float q[32];
    const float* qr = qkv + (size_t)(t0 + i) * 288 + h * 32;
    #pragma unroll
    for (int d = 0; d < 32; d++) q[d] = qr[d];

    const int ri = i / 7, ci = i % 7;
    const int li = labs[i];

    float s[49];
    float mx = -1e30f;
    for (int j = 0; j < 49; j++) {
        const float* kr = &Ks[(h * 49 + j) * 32];
        float dot = 0.0f;
        #pragma unroll
        for (int d = 0; d < 32; d++) dot = fmaf(q[d], kr[d], dot);
        int rj = j / 7, cj = j % 7;
        int idx = (ri - rj + 6) * 13 + (ci - cj + 6);
        dot += rpbs[idx * 3 + h];
        if (labs[j] != li) dot -= 100.0f;
        s[j] = dot;
        mx = fmaxf(mx, dot);
    }
    float sum = 0.0f;
    for (int j = 0; j < 49; j++) { s[j] = __expf(s[j] - mx); sum += s[j]; }
    float inv = 1.0f / sum;

    float accv[32];
    #pragma unroll
    for (int d = 0; d < 32; d++) accv[d] = 0.0f;
    for (int j = 0; j < 49; j++) {
        float p = s[j] * inv;
        const float* vr = &Vs[(h * 49 + j) * 32];
        #pragma unroll
        for (int d = 0; d < 32; d++) accv[d] = fmaf(p, vr[d], accv[d]);
    }
    float* orow = out + (size_t)(t0 + i) * 96 + h * 32;
    #pragma unroll
    for (int d = 0; d < 32; d++) orow[d] = accv[d];
}

// ---------------------------------------------------------------------------
extern "C" void kernel_launch(void* const* d_in, const int* in_sizes, int n_in,
                              void* d_out, int out_size) {
    const float* x      = (const float*)d_in[0];
    const float* n1g    = (const float*)d_in[1];
    const float* n1b    = (const float*)d_in[2];
    const float* qkv_w  = (const float*)d_in[3];
    const float* qkv_b  = (const float*)d_in[4];
    const float* rpb    = (const float*)d_in[5];
    const float* proj_w = (const float*)d_in[6];
    const float* proj_b = (const float*)d_in[7];
    const float* n2g    = (const float*)d_in[8];
    const float* n2b    = (const float*)d_in[9];
    const float* fc1_w  = (const float*)d_in[10];
    const float* fc1_b  = (const float*)d_in[11];
    const float* fc2_w  = (const float*)d_in[12];
    const float* fc2_b  = (const float*)d_in[13];
    float* out = (float*)d_out;

    float *buf1, *buf2;
    cudaGetSymbolAddress((void**)&buf1, g_buf1);
    cudaGetSymbolAddress((void**)&buf2, g_buf2);

    // 1) LN1 + shift + window partition -> buf2 [T,96]
    ln_kernel<<<TKN / 8, 256>>>(x, n1g, n1b, buf2, 1);
    // 2) QKV GEMM (q pre-scaled) -> buf1 [T,288]
    gemm_kernel<0><<<dim3(3136, 3), 256>>>(buf2, qkv_w, qkv_b, buf1, nullptr, 96);
    // 3) windowed attention -> buf2 [T,96]
    attn_kernel<<<4096, 160>>>(buf1, rpb, buf2);
    // 4) proj GEMM + window reverse + unshift + residual -> d_out [T,96]
    gemm_kernel<1><<<dim3(3136, 1), 256>>>(buf2, proj_w, proj_b, out, x, 96);
    // 5) LN2 -> buf2 [T,96]
    ln_kernel<<<TKN / 8, 256>>>(out, n2g, n2b, buf2, 0);
    // 6) FC1 + GELU -> buf1 [T,384]
    gemm_kernel<2><<<dim3(3136, 4), 256>>>(buf2, fc1_w, fc1_b, buf1, nullptr, 96);
    // 7) FC2 + residual accumulate into d_out
    gemm_kernel<3><<<dim3(3136, 1), 256>>>(buf1, fc2_w, fc2_b, out, nullptr, 384);
}

// round 3
// speedup vs baseline: 2.5371x; 2.5371x over previous
#include <cuda_runtime.h>
#include <cuda_bf16.h>
#include <mma.h>
#include <math.h>
#include <cstdint>

using namespace nvcuda;

#define TKN    200704
#define QSCALE 0.17677669529663688f

// Scratch (allocation-free): bf16 activations
__device__ __nv_bfloat16 g_buf1[200704 * 384];  // qkv [T,288] then fc1-out [T,384]
__device__ __nv_bfloat16 g_buf2[200704 * 96];   // ln1-out, attn-out, ln2-out [T,96]

// ---------------------------------------------------------------------------
// LN kernel: one warp per token; bf16 output. shifted=1 applies cyclic shift +
// window partition to the SOURCE index.
// ---------------------------------------------------------------------------
__global__ void ln_kernel(const float* __restrict__ x, const float* __restrict__ g,
                          const float* __restrict__ b, __nv_bfloat16* __restrict__ out,
                          int shifted) {
    int warp = (blockIdx.x * blockDim.x + threadIdx.x) >> 5;
    int lane = threadIdx.x & 31;
    if (warp >= TKN) return;
    int src = warp;
    if (shifted) {
        int bi  = warp / 3136;
        int rem = warp % 3136;
        int w   = rem / 49, n = rem % 49;
        int wh = w >> 3, ww = w & 7;
        int r = n / 7, cc = n % 7;
        int sh = wh * 7 + r + 3;  if (sh >= 56) sh -= 56;
        int sw = ww * 7 + cc + 3; if (sw >= 56) sw -= 56;
        src = bi * 3136 + sh * 56 + sw;
    }
    const float* xr = x + (size_t)src * 96;
    float v0 = xr[lane], v1 = xr[lane + 32], v2 = xr[lane + 64];
    float s  = v0 + v1 + v2;
    float s2 = v0 * v0 + v1 * v1 + v2 * v2;
    #pragma unroll
    for (int o = 16; o; o >>= 1) {
        s  += __shfl_xor_sync(0xffffffffu, s,  o);
        s2 += __shfl_xor_sync(0xffffffffu, s2, o);
    }
    float mean = s * (1.0f / 96.0f);
    float var  = s2 * (1.0f / 96.0f) - mean * mean;
    float rs   = rsqrtf(var + 1e-5f);
    __nv_bfloat16* orow = out + (size_t)warp * 96;
    orow[lane]      = __float2bfloat16((v0 - mean) * rs * g[lane]      + b[lane]);
    orow[lane + 32] = __float2bfloat16((v1 - mean) * rs * g[lane + 32] + b[lane + 32]);
    orow[lane + 64] = __float2bfloat16((v2 - mean) * rs * g[lane + 64] + b[lane + 64]);
}

// ---------------------------------------------------------------------------
// HMMA (wmma) GEMM: C[128,96] = A[128,K](bf16) @ W[96,K](fp32->bf16)^T + epi.
// Full K resident in smem. 8 warps (4x2), warp tile 32x48, wmma 16x16x16 bf16.
// Accumulators staged through smem fp32 for the scalar epilogue.
// MODE 0: qkv  -> bf16 [T,288], q cols scaled
// MODE 1: proj -> fp32 d_out scatter (window reverse + unshift) + residual x
// MODE 2: fc1  -> exact GELU, bf16 [T,384]
// MODE 3: fc2  -> accumulate fp32 into d_out [T,96]
// ---------------------------------------------------------------------------
template <int MODE, int K, int NOUT>
__global__ void __launch_bounds__(256)
tc_gemm(const __nv_bfloat16* __restrict__ A, const float* __restrict__ W,
        const float* __restrict__ bias, void* __restrict__ outv,
        const float* __restrict__ resid) {
    constexpr int LDA = K + 8;       // bf16 elements (multiple of 8)
    constexpr int LDC = 100;         // fp32 elements (multiple of 4)
    extern __shared__ char smem[];
    __nv_bfloat16* As = reinterpret_cast<__nv_bfloat16*>(smem);
    __nv_bfloat16* Bs = As + 128 * LDA;
    float*         Cs = reinterpret_cast<float*>(smem);

    const int tid  = threadIdx.x;
    const int row0 = blockIdx.x * 128;
    const int nb   = blockIdx.y;     // 96-col block

    // ---- load A [128,K] bf16 (vectorized 8 elems) ----
    const uint4* Ag = reinterpret_cast<const uint4*>(A + (size_t)row0 * K);
    for (int i = tid; i < 128 * (K / 8); i += 256) {
        int r = i / (K / 8), c8 = i % (K / 8);
        *reinterpret_cast<uint4*>(As + r * LDA + c8 * 8) = Ag[(size_t)r * (K / 8) + c8];
    }
    // ---- load B [96,K] from fp32 weights, convert to bf16 ----
    for (int i = tid; i < 96 * (K / 2); i += 256) {
        int r = i / (K / 2), wc = i % (K / 2);
        float2 f = *reinterpret_cast<const float2*>(W + (size_t)(nb * 96 + r) * K + wc * 2);
        __nv_bfloat162 h2 = __float22bfloat162_rn(f);
        *reinterpret_cast<uint32_t*>(Bs + r * LDA + wc * 2) = *reinterpret_cast<uint32_t*>(&h2);
    }
    __syncthreads();

    // ---- HMMA compute: warp (wm, wn) owns rows wm*32..+32, cols wn*48..+48 ----
    const int wid = tid >> 5;
    const int wm = wid & 3, wn = wid >> 2;

    wmma::fragment<wmma::accumulator, 16, 16, 16, float> c[2][3];
    #pragma unroll
    for (int i = 0; i < 2; i++)
        #pragma unroll
        for (int j = 0; j < 3; j++) wmma::fill_fragment(c[i][j], 0.0f);

    #pragma unroll 2
    for (int k = 0; k < K; k += 16) {
        wmma::fragment<wmma::matrix_a, 16, 16, 16, __nv_bfloat16, wmma::row_major> a0, a1;
        wmma::load_matrix_sync(a0, As + (wm * 32)      * LDA + k, LDA);
        wmma::load_matrix_sync(a1, As + (wm * 32 + 16) * LDA + k, LDA);
        #pragma unroll
        for (int j = 0; j < 3; j++) {
            wmma::fragment<wmma::matrix_b, 16, 16, 16, __nv_bfloat16, wmma::col_major> bf;
            wmma::load_matrix_sync(bf, Bs + (wn * 48 + j * 16) * LDA + k, LDA);
            wmma::mma_sync(c[0][j], a0, bf, c[0][j]);
            wmma::mma_sync(c[1][j], a1, bf, c[1][j]);
        }
    }
    __syncthreads();   // done reading As/Bs; Cs may overwrite

    #pragma unroll
    for (int i = 0; i < 2; i++)
        #pragma unroll
        for (int j = 0; j < 3; j++)
            wmma::store_matrix_sync(Cs + (wm * 32 + i * 16) * LDC + wn * 48 + j * 16,
                                    c[i][j], LDC, wmma::mem_row_major);
    __syncthreads();

    // ---- epilogue: thread = (ty: 8 rows, tx: 6 cols) ----
    const int tx = tid & 15;
    const int ty = tid >> 4;
    #pragma unroll
    for (int i = 0; i < 8; i++) {
        int lr  = ty * 8 + i;
        int row = row0 + lr;
        int dst = row;
        if (MODE == 1) {
            int bi  = row / 3136;
            int rem = row % 3136;
            int ww_ = rem / 49, n = rem % 49;
            int wh = ww_ >> 3, wcl = ww_ & 7;
            int r7 = n / 7, c7 = n % 7;
            int hh = wh * 7 + r7 + 3;  if (hh >= 56) hh -= 56;
            int zz = wcl * 7 + c7 + 3; if (zz >= 56) zz -= 56;
            dst = bi * 3136 + hh * 56 + zz;
        }
        #pragma unroll
        for (int j = 0; j < 6; j++) {
            int lc  = tx * 6 + j;
            int col = nb * 96 + lc;
            float v = Cs[lr * LDC + lc] + bias[col];
            if (MODE == 0) {
                if (col < 96) v *= QSCALE;
                ((__nv_bfloat16*)outv)[(size_t)row * NOUT + col] = __float2bfloat16(v);
            } else if (MODE == 1) {
                size_t o = (size_t)dst * 96 + col;
                ((float*)outv)[o] = resid[o] + v;
            } else if (MODE == 2) {
                v = 0.5f * v * (1.0f + erff(v * 0.70710678118654752f));
                ((__nv_bfloat16*)outv)[(size_t)row * NOUT + col] = __float2bfloat16(v);
            } else {
                ((float*)outv)[(size_t)row * 96 + col] += v;
            }
        }
    }
}

// ---------------------------------------------------------------------------
// Windowed attention: one block per window. thread=(head,row). bf16 in/out,
// fp32 math, float4 smem reads.
// ---------------------------------------------------------------------------
__global__ void attn_kernel(const __nv_bfloat16* __restrict__ qkv,
                            const float* __restrict__ rpb,
                            __nv_bfloat16* __restrict__ out) {
    __shared__ __align__(16) float Ks[3 * 49 * 32];
    __shared__ __align__(16) float Vs[3 * 49 * 32];
    __shared__ float rpbs[169 * 3];
    __shared__ int   labs[49];

    const int wb  = blockIdx.x;
    const int t0  = wb * 49;
    const int tid = threadIdx.x;

    for (int i = tid; i < 49 * 48; i += blockDim.x) {
        int r = i / 48, wd = i % 48;
        int c = wd * 2, h = c >> 5, d = c & 31;
        const __nv_bfloat162* kb = reinterpret_cast<const __nv_bfloat162*>(qkv + (size_t)(t0 + r) * 288 + 96);
        const __nv_bfloat162* vb = reinterpret_cast<const __nv_bfloat162*>(qkv + (size_t)(t0 + r) * 288 + 192);
        float2 kf = __bfloat1622float2(kb[wd]);
        float2 vf = __bfloat1622float2(vb[wd]);
        Ks[(h * 49 + r) * 32 + d]     = kf.x;
        Ks[(h * 49 + r) * 32 + d + 1] = kf.y;
        Vs[(h * 49 + r) * 32 + d]     = vf.x;
        Vs[(h * 49 + r) * 32 + d + 1] = vf.y;
    }
    for (int i = tid; i < 169 * 3; i += blockDim.x) rpbs[i] = rpb[i];

    const int w  = wb & 63;
    const int wh = w >> 3, ww = w & 7;
    if (tid < 49) {
        int r = tid / 7, cc = tid % 7;
        int hh = wh * 7 + r, zz = ww * 7 + cc;
        int rh = (hh < 49) ? 0 : ((hh < 53) ? 1 : 2);
        int rw = (zz < 49) ? 0 : ((zz < 53) ? 1 : 2);
        labs[tid] = rh * 3 + rw;
    }
    __syncthreads();
    if (tid >= 147) return;

    const int h = tid / 49, i = tid % 49;
    float q[32];
    {
        const __nv_bfloat162* qw = reinterpret_cast<const __nv_bfloat162*>(qkv + (size_t)(t0 + i) * 288 + h * 32);
        #pragma unroll
        for (int d2 = 0; d2 < 16; d2++) {
            float2 f = __bfloat1622float2(qw[d2]);
            q[2 * d2] = f.x; q[2 * d2 + 1] = f.y;
        }
    }

    const int ri = i / 7, ci = i % 7;
    const int li = labs[i];

    float s[49];
    float mx = -1e30f;
    for (int j = 0; j < 49; j++) {
        const float4* kr = reinterpret_cast<const float4*>(&Ks[(h * 49 + j) * 32]);
        float dot = 0.0f;
        #pragma unroll
        for (int d4 = 0; d4 < 8; d4++) {
            float4 kk = kr[d4];
            dot = fmaf(q[4 * d4 + 0], kk.x, dot);
            dot = fmaf(q[4 * d4 + 1], kk.y, dot);
            dot = fmaf(q[4 * d4 + 2], kk.z, dot);
            dot = fmaf(q[4 * d4 + 3], kk.w, dot);
        }
        int rj = j / 7, cj = j % 7;
        dot += rpbs[((ri - rj + 6) * 13 + (ci - cj + 6)) * 3 + h];
        if (labs[j] != li) dot -= 100.0f;
        s[j] = dot;
        mx = fmaxf(mx, dot);
    }
    float sum = 0.0f;
    for (int j = 0; j < 49; j++) { s[j] = __expf(s[j] - mx); sum += s[j]; }
    float inv = 1.0f / sum;

    float4 acc[8];
    #pragma unroll
    for (int d4 = 0; d4 < 8; d4++) acc[d4] = make_float4(0.f, 0.f, 0.f, 0.f);
    for (int j = 0; j < 49; j++) {
        float p = s[j] * inv;
        const float4* vr = reinterpret_cast<const float4*>(&Vs[(h * 49 + j) * 32]);
        #pragma unroll
        for (int d4 = 0; d4 < 8; d4++) {
            float4 vv = vr[d4];
            acc[d4].x = fmaf(p, vv.x, acc[d4].x);
            acc[d4].y = fmaf(p, vv.y, acc[d4].y);
            acc[d4].z = fmaf(p, vv.z, acc[d4].z);
            acc[d4].w = fmaf(p, vv.w, acc[d4].w);
        }
    }
    uint32_t* orow = reinterpret_cast<uint32_t*>(out + (size_t)(t0 + i) * 96 + h * 32);
    #pragma unroll
    for (int d4 = 0; d4 < 8; d4++) {
        __nv_bfloat162 p0 = __floats2bfloat162_rn(acc[d4].x, acc[d4].y);
        __nv_bfloat162 p1 = __floats2bfloat162_rn(acc[d4].z, acc[d4].w);
        orow[2 * d4]     = *reinterpret_cast<uint32_t*>(&p0);
        orow[2 * d4 + 1] = *reinterpret_cast<uint32_t*>(&p1);
    }
}

// ---------------------------------------------------------------------------
extern "C" void kernel_launch(void* const* d_in, const int* in_sizes, int n_in,
                              void* d_out, int out_size) {
    const float* x      = (const float*)d_in[0];
    const float* n1g    = (const float*)d_in[1];
    const float* n1b    = (const float*)d_in[2];
    const float* qkv_w  = (const float*)d_in[3];
    const float* qkv_b  = (const float*)d_in[4];
    const float* rpb    = (const float*)d_in[5];
    const float* proj_w = (const float*)d_in[6];
    const float* proj_b = (const float*)d_in[7];
    const float* n2g    = (const float*)d_in[8];
    const float* n2b    = (const float*)d_in[9];
    const float* fc1_w  = (const float*)d_in[10];
    const float* fc1_b  = (const float*)d_in[11];
    const float* fc2_w  = (const float*)d_in[12];
    const float* fc2_b  = (const float*)d_in[13];
    float* out = (float*)d_out;

    __nv_bfloat16 *buf1, *buf2;
    cudaGetSymbolAddress((void**)&buf1, g_buf1);
    cudaGetSymbolAddress((void**)&buf2, g_buf2);

    // smem sizes: max(load phase, fp32 C staging = 128*100*4 = 51200)
    const int smem_k96  = 51200;                       // (128+96)*104*2=46592 < 51200
    const int smem_k384 = (128 + 96) * 392 * 2;        // 175616 > 51200
    cudaFuncSetAttribute(tc_gemm<0, 96, 288>,  cudaFuncAttributeMaxDynamicSharedMemorySize, smem_k96);
    cudaFuncSetAttribute(tc_gemm<1, 96, 96>,   cudaFuncAttributeMaxDynamicSharedMemorySize, smem_k96);
    cudaFuncSetAttribute(tc_gemm<2, 96, 384>,  cudaFuncAttributeMaxDynamicSharedMemorySize, smem_k96);
    cudaFuncSetAttribute(tc_gemm<3, 384, 96>,  cudaFuncAttributeMaxDynamicSharedMemorySize, smem_k384);

    // 1) LN1 + shift + window partition -> buf2 bf16 [T,96]
    ln_kernel<<<TKN / 8, 256>>>(x, n1g, n1b, buf2, 1);
    // 2) QKV GEMM (q pre-scaled) -> buf1 bf16 [T,288]
    tc_gemm<0, 96, 288><<<dim3(1568, 3), 256, smem_k96>>>(buf2, qkv_w, qkv_b, buf1, nullptr);
    // 3) windowed attention -> buf2 bf16 [T,96]
    attn_kernel<<<4096, 160>>>(buf1, rpb, buf2);
    // 4) proj GEMM + window reverse + unshift + residual -> d_out fp32 [T,96]
    tc_gemm<1, 96, 96><<<dim3(1568, 1), 256, smem_k96>>>(buf2, proj_w, proj_b, out, x);
    // 5) LN2 -> buf2 bf16 [T,96]
    ln_kernel<<<TKN / 8, 256>>>(out, n2g, n2b, buf2, 0);
    // 6) FC1 + GELU -> buf1 bf16 [T,384]
    tc_gemm<2, 96, 384><<<dim3(1568, 4), 256, smem_k96>>>(buf2, fc1_w, fc1_b, buf1, nullptr);
    // 7) FC2 + accumulate into d_out
    tc_gemm<3, 384, 96><<<dim3(1568, 1), 256, smem_k384>>>(buf1, fc2_w, fc2_b, out, nullptr);
}

// round 4
// speedup vs baseline: 3.6337x; 1.4322x over previous
#include <cuda_runtime.h>
#include <cuda_bf16.h>
#include <math.h>
#include <cstdint>

#define TKN    200704
#define QSCALE 0.17677669529663688f

// Scratch (allocation-free): bf16 activations + pre-converted weights
__device__ __nv_bfloat16 g_buf1[200704 * 384];  // qkv [T,288] then fc1-out [T,384]
__device__ __nv_bfloat16 g_buf2[200704 * 96];   // ln1-out, attn-out, ln2-out [T,96]
__device__ __nv_bfloat16 g_wbuf[110592];        // qkv_w | proj_w | fc1_w | fc2_w (bf16)

#define WOFF_QKV  0
#define WOFF_PROJ 27648
#define WOFF_FC1  36864
#define WOFF_FC2  73728

// ---------------------------------------------------------------------------
// PTX helpers
// ---------------------------------------------------------------------------
__device__ __forceinline__ uint32_t smem_u32(const void* p) {
    uint32_t a;
    asm("{ .reg .u64 t; cvta.to.shared.u64 t, %1; cvt.u32.u64 %0, t; }" : "=r"(a) : "l"(p));
    return a;
}
__device__ __forceinline__ void cp8(uint32_t dst, const void* src) {
    asm volatile("cp.async.ca.shared.global [%0], [%1], 8;" :: "r"(dst), "l"(src));
}
#define CP_COMMIT() asm volatile("cp.async.commit_group;" ::: "memory")
__device__ __forceinline__ void ldm_x4(uint32_t& r0, uint32_t& r1, uint32_t& r2, uint32_t& r3,
                                       uint32_t addr) {
    asm volatile("ldmatrix.sync.aligned.m8n8.x4.shared.b16 {%0,%1,%2,%3}, [%4];"
                 : "=r"(r0), "=r"(r1), "=r"(r2), "=r"(r3) : "r"(addr));
}
__device__ __forceinline__ void mma_bf16(float* c, uint32_t a0, uint32_t a1, uint32_t a2,
                                         uint32_t a3, uint32_t b0, uint32_t b1) {
    asm volatile("mma.sync.aligned.m16n8k16.row.col.f32.bf16.bf16.f32 "
                 "{%0,%1,%2,%3}, {%4,%5,%6,%7}, {%8,%9}, {%0,%1,%2,%3};"
                 : "+f"(c[0]), "+f"(c[1]), "+f"(c[2]), "+f"(c[3])
                 : "r"(a0), "r"(a1), "r"(a2), "r"(a3), "r"(b0), "r"(b1));
}

// ---------------------------------------------------------------------------
// Weight pre-convert fp32 -> bf16 (runs every call; deterministic)
// ---------------------------------------------------------------------------
__global__ void wconv(const float* __restrict__ a, const float* __restrict__ b,
                      const float* __restrict__ c, const float* __restrict__ d,
                      __nv_bfloat16* __restrict__ o) {
    int i = blockIdx.x * 256 + threadIdx.x;
    if (i < 27648)       o[i] = __float2bfloat16(a[i]);
    else if (i < 36864)  o[i] = __float2bfloat16(b[i - 27648]);
    else if (i < 73728)  o[i] = __float2bfloat16(c[i - 36864]);
    else if (i < 110592) o[i] = __float2bfloat16(d[i - 73728]);
}

// ---------------------------------------------------------------------------
// LN kernel: one warp per token; bf16 out. shifted=1: gather through cyclic
// shift + window partition.
// ---------------------------------------------------------------------------
__global__ void ln_kernel(const float* __restrict__ x, const float* __restrict__ g,
                          const float* __restrict__ b, __nv_bfloat16* __restrict__ out,
                          int shifted) {
    int warp = (blockIdx.x * blockDim.x + threadIdx.x) >> 5;
    int lane = threadIdx.x & 31;
    if (warp >= TKN) return;
    int src = warp;
    if (shifted) {
        int bi  = warp / 3136;
        int rem = warp % 3136;
        int w   = rem / 49, n = rem % 49;
        int wh = w >> 3, ww = w & 7;
        int r = n / 7, cc = n % 7;
        int sh = wh * 7 + r + 3;  if (sh >= 56) sh -= 56;
        int sw = ww * 7 + cc + 3; if (sw >= 56) sw -= 56;
        src = bi * 3136 + sh * 56 + sw;
    }
    const float* xr = x + (size_t)src * 96;
    float v0 = xr[lane], v1 = xr[lane + 32], v2 = xr[lane + 64];
    float s  = v0 + v1 + v2;
    float s2 = v0 * v0 + v1 * v1 + v2 * v2;
    #pragma unroll
    for (int o = 16; o; o >>= 1) {
        s  += __shfl_xor_sync(0xffffffffu, s,  o);
        s2 += __shfl_xor_sync(0xffffffffu, s2, o);
    }
    float mean = s * (1.0f / 96.0f);
    float var  = s2 * (1.0f / 96.0f) - mean * mean;
    float rs   = rsqrtf(var + 1e-5f);
    __nv_bfloat16* orow = out + (size_t)warp * 96;
    orow[lane]      = __float2bfloat16((v0 - mean) * rs * g[lane]      + b[lane]);
    orow[lane + 32] = __float2bfloat16((v1 - mean) * rs * g[lane + 32] + b[lane + 32]);
    orow[lane + 64] = __float2bfloat16((v2 - mean) * rs * g[lane + 64] + b[lane + 64]);
}

// ---------------------------------------------------------------------------
// Pipelined HMMA GEMM. Per CTA: TILES row-tiles of 128; full N=96 col-block
// (blockIdx.y selects which 96-col slice of the weight). K processed in
// chunks of 96 (KCH chunks). A (and B when KCH>1) double-buffered via
// cp.async; epilogue directly from mma fragments.
// MODE 0: qkv  -> bf16 [T,288], q cols scaled
// MODE 1: proj -> fp32 d_out scatter (window reverse + unshift) + residual
// MODE 2: fc1  -> exact GELU, bf16 [T,384]
// MODE 3: fc2  -> accumulate fp32 into d_out [T,96]
// ---------------------------------------------------------------------------
template <int MODE, int KGLOB, int KCH, int NOUT, int TILES>
__global__ void __launch_bounds__(256)
tc_gemm(const __nv_bfloat16* __restrict__ A, const __nv_bfloat16* __restrict__ Wb,
        const float* __restrict__ bias, void* __restrict__ outv,
        const float* __restrict__ resid) {
    constexpr bool BRES = (KCH == 1);
    constexpr int ABYTES = 128 * 104 * 2;   // 26624
    constexpr int BBYTES = 96 * 104 * 2;    // 19968
    extern __shared__ char smem[];
    const uint32_t sbase = smem_u32(smem);
    const uint32_t Ab0 = sbase, Ab1 = sbase + ABYTES;
    const uint32_t Bb0 = sbase + 2 * ABYTES;
    const uint32_t Bb1 = BRES ? Bb0 : Bb0 + BBYTES;

    const int tid   = threadIdx.x;
    const int lane  = tid & 31;
    const int wid   = tid >> 5;
    const int wm    = wid & 3;
    const int wn    = wid >> 2;
    const int nb    = blockIdx.y;
    const int tile0 = blockIdx.x * TILES;
    const int NSTEP = TILES * KCH;

    auto issueA = [&](int s) {
        int tile = s / KCH, kc = s % KCH;
        const __nv_bfloat16* src = A + (size_t)(tile0 + tile) * 128 * KGLOB + kc * 96;
        uint32_t dst = (s & 1) ? Ab1 : Ab0;
        #pragma unroll
        for (int i = tid; i < 128 * 24; i += 256) {
            int r = i / 24, c = i % 24;
            cp8(dst + r * 208 + c * 8, src + (size_t)r * KGLOB + c * 4);
        }
    };
    auto issueB = [&](int s) {
        int kc = s % KCH;
        const __nv_bfloat16* src = Wb + (size_t)nb * 96 * KGLOB + kc * 96;
        uint32_t dst = (s & 1) ? Bb1 : Bb0;
        #pragma unroll
        for (int i = tid; i < 96 * 24; i += 256) {
            int r = i / 24, c = i % 24;
            cp8(dst + r * 208 + c * 8, src + (size_t)r * KGLOB + c * 4);
        }
    };

    issueA(0); issueB(0); CP_COMMIT();

    float acc[2][6][4];

    for (int s = 0; s < NSTEP; s++) {
        const int kc = s % KCH, tile = s / KCH;
        const bool hasnext = (s + 1 < NSTEP);
        if (hasnext) {
            issueA(s + 1);
            if (!BRES) issueB(s + 1);
            CP_COMMIT();
            asm volatile("cp.async.wait_group 1;" ::: "memory");
        } else {
            asm volatile("cp.async.wait_group 0;" ::: "memory");
        }
        __syncthreads();

        if (kc == 0) {
            #pragma unroll
            for (int m = 0; m < 2; m++)
                #pragma unroll
                for (int n = 0; n < 6; n++)
                    #pragma unroll
                    for (int v = 0; v < 4; v++) acc[m][n][v] = 0.0f;
        }

        const uint32_t abase = (s & 1) ? Ab1 : Ab0;
        const uint32_t bbase = BRES ? Bb0 : ((s & 1) ? Bb1 : Bb0);

        #pragma unroll
        for (int kk = 0; kk < 6; kk++) {
            const int k = kk * 16;
            uint32_t a[2][4];
            #pragma unroll
            for (int m = 0; m < 2; m++)
                ldm_x4(a[m][0], a[m][1], a[m][2], a[m][3],
                       abase + ((uint32_t)((wm * 32 + m * 16 + (lane & 15)) * 104
                                           + k + (lane >> 4) * 8) << 1));
            #pragma unroll
            for (int g = 0; g < 3; g++) {
                uint32_t b0, b1, b2, b3;
                ldm_x4(b0, b1, b2, b3,
                       bbase + ((uint32_t)((wn * 48 + g * 16 + (lane & 15)) * 104
                                           + k + (lane >> 4) * 8) << 1));
                #pragma unroll
                for (int m = 0; m < 2; m++) {
                    mma_bf16(acc[m][g * 2],     a[m][0], a[m][1], a[m][2], a[m][3], b0, b2);
                    mma_bf16(acc[m][g * 2 + 1], a[m][0], a[m][1], a[m][2], a[m][3], b1, b3);
                }
            }
        }

        if (kc == KCH - 1) {
            const int row0 = (tile0 + tile) * 128 + wm * 32;
            const int colb = nb * 96 + wn * 48;
            #pragma unroll
            for (int m = 0; m < 2; m++) {
                const int ra = row0 + m * 16 + (lane >> 2);
                const int rb = ra + 8;
                int da = ra, db = rb;
                if (MODE == 1) {
                    #pragma unroll
                    for (int t2 = 0; t2 < 2; t2++) {
                        int row = t2 ? rb : ra;
                        int bi  = row / 3136;
                        int rem = row % 3136;
                        int ww_ = rem / 49, n = rem % 49;
                        int wh = ww_ >> 3, wcl = ww_ & 7;
                        int r7 = n / 7, c7 = n % 7;
                        int hh = wh * 7 + r7 + 3;  if (hh >= 56) hh -= 56;
                        int zz = wcl * 7 + c7 + 3; if (zz >= 56) zz -= 56;
                        int d = bi * 3136 + hh * 56 + zz;
                        if (t2) db = d; else da = d;
                    }
                }
                #pragma unroll
                for (int n = 0; n < 6; n++) {
                    const int col = colb + n * 8 + (lane & 3) * 2;
                    float bi0 = __ldg(bias + col), bi1 = __ldg(bias + col + 1);
                    float v00 = acc[m][n][0] + bi0, v01 = acc[m][n][1] + bi1;
                    float v10 = acc[m][n][2] + bi0, v11 = acc[m][n][3] + bi1;
                    if (MODE == 0) {
                        if (col < 96) { v00 *= QSCALE; v01 *= QSCALE; v10 *= QSCALE; v11 *= QSCALE; }
                        __nv_bfloat162 p0 = __floats2bfloat162_rn(v00, v01);
                        __nv_bfloat162 p1 = __floats2bfloat162_rn(v10, v11);
                        __nv_bfloat16* out = (__nv_bfloat16*)outv;
                        *reinterpret_cast<uint32_t*>(out + (size_t)ra * NOUT + col) = *reinterpret_cast<uint32_t*>(&p0);
                        *reinterpret_cast<uint32_t*>(out + (size_t)rb * NOUT + col) = *reinterpret_cast<uint32_t*>(&p1);
                    } else if (MODE == 1) {
                        float* out = (float*)outv;
                        size_t oa = (size_t)da * 96 + col, ob = (size_t)db * 96 + col;
                        float2 r0 = *reinterpret_cast<const float2*>(resid + oa);
                        float2 r1 = *reinterpret_cast<const float2*>(resid + ob);
                        float2 w0 = make_float2(r0.x + v00, r0.y + v01);
                        float2 w1 = make_float2(r1.x + v10, r1.y + v11);
                        *reinterpret_cast<float2*>(out + oa) = w0;
                        *reinterpret_cast<float2*>(out + ob) = w1;
                    } else if (MODE == 2) {
                        v00 = 0.5f * v00 * (1.0f + erff(v00 * 0.70710678118654752f));
                        v01 = 0.5f * v01 * (1.0f + erff(v01 * 0.70710678118654752f));
                        v10 = 0.5f * v10 * (1.0f + erff(v10 * 0.70710678118654752f));
                        v11 = 0.5f * v11 * (1.0f + erff(v11 * 0.70710678118654752f));
                        __nv_bfloat162 p0 = __floats2bfloat162_rn(v00, v01);
                        __nv_bfloat162 p1 = __floats2bfloat162_rn(v10, v11);
                        __nv_bfloat16* out = (__nv_bfloat16*)outv;
                        *reinterpret_cast<uint32_t*>(out + (size_t)ra * NOUT + col) = *reinterpret_cast<uint32_t*>(&p0);
                        *reinterpret_cast<uint32_t*>(out + (size_t)rb * NOUT + col) = *reinterpret_cast<uint32_t*>(&p1);
                    } else {
                        float* out = (float*)outv;
                        size_t oa = (size_t)ra * 96 + col, ob = (size_t)rb * 96 + col;
                        float2 r0 = *reinterpret_cast<const float2*>(out + oa);
                        float2 r1 = *reinterpret_cast<const float2*>(out + ob);
                        r0.x += v00; r0.y += v01; r1.x += v10; r1.y += v11;
                        *reinterpret_cast<float2*>(out + oa) = r0;
                        *reinterpret_cast<float2*>(out + ob) = r1;
                    }
                }
            }
        }
        __syncthreads();
    }
}

// ---------------------------------------------------------------------------
// Windowed attention: block per window, thread=(head,row). Scores in smem
// (stride 49 = conflict-free) instead of per-thread local arrays.
// ---------------------------------------------------------------------------
__global__ void attn_kernel(const __nv_bfloat16* __restrict__ qkv,
                            const float* __restrict__ rpb,
                            __nv_bfloat16* __restrict__ out) {
    extern __shared__ float ash[];
    float* Ks   = ash;            // 3*49*32 = 4704
    float* Vs   = Ks + 4704;      // 4704
    float* Sc   = Vs + 4704;      // 147*49 = 7203
    float* rpbs = Sc + 7203;      // 507
    int*   labs = (int*)(rpbs + 507);  // 49

    const int wb  = blockIdx.x;
    const int t0  = wb * 49;
    const int tid = threadIdx.x;

    for (int i = tid; i < 49 * 48; i += blockDim.x) {
        int r = i / 48, wd = i % 48;
        int c = wd * 2, h = c >> 5, d = c & 31;
        const __nv_bfloat162* kb = reinterpret_cast<const __nv_bfloat162*>(qkv + (size_t)(t0 + r) * 288 + 96);
        const __nv_bfloat162* vb = reinterpret_cast<const __nv_bfloat162*>(qkv + (size_t)(t0 + r) * 288 + 192);
        float2 kf = __bfloat1622float2(kb[wd]);
        float2 vf = __bfloat1622float2(vb[wd]);
        Ks[(h * 49 + r) * 32 + d]     = kf.x;
        Ks[(h * 49 + r) * 32 + d + 1] = kf.y;
        Vs[(h * 49 + r) * 32 + d]     = vf.x;
        Vs[(h * 49 + r) * 32 + d + 1] = vf.y;
    }
    for (int i = tid; i < 169 * 3; i += blockDim.x) rpbs[i] = rpb[i];

    const int w  = wb & 63;
    const int wh = w >> 3, ww = w & 7;
    if (tid < 49) {
        int r = tid / 7, cc = tid % 7;
        int hh = wh * 7 + r, zz = ww * 7 + cc;
        int rh = (hh < 49) ? 0 : ((hh < 53) ? 1 : 2);
        int rw = (zz < 49) ? 0 : ((zz < 53) ? 1 : 2);
        labs[tid] = rh * 3 + rw;
    }
    __syncthreads();
    if (tid >= 147) return;

    const int h = tid / 49, i = tid % 49;
    float q[32];
    {
        const __nv_bfloat162* qw = reinterpret_cast<const __nv_bfloat162*>(qkv + (size_t)(t0 + i) * 288 + h * 32);
        #pragma unroll
        for (int d2 = 0; d2 < 16; d2++) {
            float2 f = __bfloat1622float2(qw[d2]);
            q[2 * d2] = f.x; q[2 * d2 + 1] = f.y;
        }
    }

    const int ri = i / 7, ci = i % 7;
    const int li = labs[i];
    float* srow = Sc + tid * 49;

    float mx = -1e30f;
    for (int j = 0; j < 49; j++) {
        const float4* kr = reinterpret_cast<const float4*>(&Ks[(h * 49 + j) * 32]);
        float dot = 0.0f;
        #pragma unroll
        for (int d4 = 0; d4 < 8; d4++) {
            float4 kk = kr[d4];
            dot = fmaf(q[4 * d4 + 0], kk.x, dot);
            dot = fmaf(q[4 * d4 + 1], kk.y, dot);
            dot = fmaf(q[4 * d4 + 2], kk.z, dot);
            dot = fmaf(q[4 * d4 + 3], kk.w, dot);
        }
        int rj = j / 7, cj = j % 7;
        dot += rpbs[((ri - rj + 6) * 13 + (ci - cj + 6)) * 3 + h];
        if (labs[j] != li) dot -= 100.0f;
        srow[j] = dot;
        mx = fmaxf(mx, dot);
    }
    float sum = 0.0f;
    for (int j = 0; j < 49; j++) {
        float e = __expf(srow[j] - mx);
        srow[j] = e;
        sum += e;
    }
    float inv = 1.0f / sum;

    float4 acc[8];
    #pragma unroll
    for (int d4 = 0; d4 < 8; d4++) acc[d4] = make_float4(0.f, 0.f, 0.f, 0.f);
    for (int j = 0; j < 49; j++) {
        float p = srow[j] * inv;
        const float4* vr = reinterpret_cast<const float4*>(&Vs[(h * 49 + j) * 32]);
        #pragma unroll
        for (int d4 = 0; d4 < 8; d4++) {
            float4 vv = vr[d4];
            acc[d4].x = fmaf(p, vv.x, acc[d4].x);
            acc[d4].y = fmaf(p, vv.y, acc[d4].y);
            acc[d4].z = fmaf(p, vv.z, acc[d4].z);
            acc[d4].w = fmaf(p, vv.w, acc[d4].w);
        }
    }
    uint32_t* orow = reinterpret_cast<uint32_t*>(out + (size_t)(t0 + i) * 96 + h * 32);
    #pragma unroll
    for (int d4 = 0; d4 < 8; d4++) {
        __nv_bfloat162 p0 = __floats2bfloat162_rn(acc[d4].x, acc[d4].y);
        __nv_bfloat162 p1 = __floats2bfloat162_rn(acc[d4].z, acc[d4].w);
        orow[2 * d4]     = *reinterpret_cast<uint32_t*>(&p0);
        orow[2 * d4 + 1] = *reinterpret_cast<uint32_t*>(&p1);
    }
}

// ---------------------------------------------------------------------------
extern "C" void kernel_launch(void* const* d_in, const int* in_sizes, int n_in,
                              void* d_out, int out_size) {
    const float* x      = (const float*)d_in[0];
    const float* n1g    = (const float*)d_in[1];
    const float* n1b    = (const float*)d_in[2];
    const float* qkv_w  = (const float*)d_in[3];
    const float* qkv_b  = (const float*)d_in[4];
    const float* rpb    = (const float*)d_in[5];
    const float* proj_w = (const float*)d_in[6];
    const float* proj_b = (const float*)d_in[7];
    const float* n2g    = (const float*)d_in[8];
    const float* n2b    = (const float*)d_in[9];
    const float* fc1_w  = (const float*)d_in[10];
    const float* fc1_b  = (const float*)d_in[11];
    const float* fc2_w  = (const float*)d_in[12];
    const float* fc2_b  = (const float*)d_in[13];
    float* out = (float*)d_out;

    __nv_bfloat16 *buf1, *buf2, *wb;
    cudaGetSymbolAddress((void**)&buf1, g_buf1);
    cudaGetSymbolAddress((void**)&buf2, g_buf2);
    cudaGetSymbolAddress((void**)&wb,   g_wbuf);

    const int smem_k96  = 2 * 26624 + 19968;        // 73216
    const int smem_k384 = 2 * 26624 + 2 * 19968;    // 93184
    const int smem_attn = 68672;
    cudaFuncSetAttribute(tc_gemm<0, 96, 1, 288, 8>,   cudaFuncAttributeMaxDynamicSharedMemorySize, smem_k96);
    cudaFuncSetAttribute(tc_gemm<1, 96, 1, 96, 4>,    cudaFuncAttributeMaxDynamicSharedMemorySize, smem_k96);
    cudaFuncSetAttribute(tc_gemm<2, 96, 1, 384, 16>,  cudaFuncAttributeMaxDynamicSharedMemorySize, smem_k96);
    cudaFuncSetAttribute(tc_gemm<3, 384, 4, 96, 4>,   cudaFuncAttributeMaxDynamicSharedMemorySize, smem_k384);
    cudaFuncSetAttribute(attn_kernel, cudaFuncAttributeMaxDynamicSharedMemorySize, smem_attn);

    // 0) weights fp32 -> bf16
    wconv<<<432, 256>>>(qkv_w, proj_w, fc1_w, fc2_w, wb);
    // 1) LN1 + shift + window partition -> buf2 bf16 [T,96]
    ln_kernel<<<TKN / 8, 256>>>(x, n1g, n1b, buf2, 1);
    // 2) QKV GEMM (q pre-scaled) -> buf1 bf16 [T,288]
    tc_gemm<0, 96, 1, 288, 8><<<dim3(196, 3), 256, smem_k96>>>(buf2, wb + WOFF_QKV, qkv_b, buf1, nullptr);
    // 3) windowed attention -> buf2 bf16 [T,96]
    attn_kernel<<<4096, 160, smem_attn>>>(buf1, rpb, buf2);
    // 4) proj GEMM + window reverse + unshift + residual -> d_out fp32 [T,96]
    tc_gemm<1, 96, 1, 96, 4><<<dim3(392, 1), 256, smem_k96>>>(buf2, wb + WOFF_PROJ, proj_b, out, x);
    // 5) LN2 -> buf2 bf16 [T,96]
    ln_kernel<<<TKN / 8, 256>>>(out, n2g, n2b, buf2, 0);
    // 6) FC1 + GELU -> buf1 bf16 [T,384]
    tc_gemm<2, 96, 1, 384, 16><<<dim3(98, 4), 256, smem_k96>>>(buf2, wb + WOFF_FC1, fc1_b, buf1, nullptr);
    // 7) FC2 + accumulate into d_out
    tc_gemm<3, 384, 4, 96, 4><<<dim3(392, 1), 256, smem_k384>>>(buf1, wb + WOFF_FC2, fc2_b, out, nullptr);
}

// round 5
// speedup vs baseline: 4.2163x; 1.1603x over previous
#include <cuda_runtime.h>
#include <cuda_bf16.h>
#include <math.h>
#include <cstdint>

#define TKN    200704
#define QSCALE 0.17677669529663688f

// Scratch (allocation-free): bf16 activations + pre-converted weights
__device__ __nv_bfloat16 g_buf1[200704 * 384];  // qkv [T,288] then fc1-out [T,384]
__device__ __nv_bfloat16 g_buf2[200704 * 96];   // ln1-out, attn-out, ln2-out [T,96]
__device__ __nv_bfloat16 g_wbuf[110592];        // qkv_w | proj_w | fc1_w | fc2_w (bf16)

#define WOFF_QKV  0
#define WOFF_PROJ 27648
#define WOFF_FC1  36864
#define WOFF_FC2  73728

// ---------------------------------------------------------------------------
// PTX helpers
// ---------------------------------------------------------------------------
__device__ __forceinline__ uint32_t smem_u32(const void* p) {
    uint32_t a;
    asm("{ .reg .u64 t; cvta.to.shared.u64 t, %1; cvt.u32.u64 %0, t; }" : "=r"(a) : "l"(p));
    return a;
}
__device__ __forceinline__ void cp8(uint32_t dst, const void* src) {
    asm volatile("cp.async.ca.shared.global [%0], [%1], 8;" :: "r"(dst), "l"(src));
}
#define CP_COMMIT() asm volatile("cp.async.commit_group;" ::: "memory")
__device__ __forceinline__ void ldm_x4(uint32_t& r0, uint32_t& r1, uint32_t& r2, uint32_t& r3,
                                       uint32_t addr) {
    asm volatile("ldmatrix.sync.aligned.m8n8.x4.shared.b16 {%0,%1,%2,%3}, [%4];"
                 : "=r"(r0), "=r"(r1), "=r"(r2), "=r"(r3) : "r"(addr));
}
__device__ __forceinline__ void ldm_x4t(uint32_t& r0, uint32_t& r1, uint32_t& r2, uint32_t& r3,
                                        uint32_t addr) {
    asm volatile("ldmatrix.sync.aligned.m8n8.x4.trans.shared.b16 {%0,%1,%2,%3}, [%4];"
                 : "=r"(r0), "=r"(r1), "=r"(r2), "=r"(r3) : "r"(addr));
}
__device__ __forceinline__ void mma_bf16(float* c, uint32_t a0, uint32_t a1, uint32_t a2,
                                         uint32_t a3, uint32_t b0, uint32_t b1) {
    asm volatile("mma.sync.aligned.m16n8k16.row.col.f32.bf16.bf16.f32 "
                 "{%0,%1,%2,%3}, {%4,%5,%6,%7}, {%8,%9}, {%0,%1,%2,%3};"
                 : "+f"(c[0]), "+f"(c[1]), "+f"(c[2]), "+f"(c[3])
                 : "r"(a0), "r"(a1), "r"(a2), "r"(a3), "r"(b0), "r"(b1));
}
__device__ __forceinline__ uint32_t packbf(float a, float b) {
    __nv_bfloat162 h = __floats2bfloat162_rn(a, b);
    return *reinterpret_cast<uint32_t*>(&h);
}

// ---------------------------------------------------------------------------
// Weight pre-convert fp32 -> bf16
// ---------------------------------------------------------------------------
__global__ void wconv(const float* __restrict__ a, const float* __restrict__ b,
                      const float* __restrict__ c, const float* __restrict__ d,
                      __nv_bfloat16* __restrict__ o) {
    int i = blockIdx.x * 256 + threadIdx.x;
    if (i < 27648)       o[i] = __float2bfloat16(a[i]);
    else if (i < 36864)  o[i] = __float2bfloat16(b[i - 27648]);
    else if (i < 73728)  o[i] = __float2bfloat16(c[i - 36864]);
    else if (i < 110592) o[i] = __float2bfloat16(d[i - 73728]);
}

// ---------------------------------------------------------------------------
// LN kernel (one warp per token, bf16 out, optional shift+partition gather)
// ---------------------------------------------------------------------------
__global__ void ln_kernel(const float* __restrict__ x, const float* __restrict__ g,
                          const float* __restrict__ b, __nv_bfloat16* __restrict__ out,
                          int shifted) {
    int warp = (blockIdx.x * blockDim.x + threadIdx.x) >> 5;
    int lane = threadIdx.x & 31;
    if (warp >= TKN) return;
    int src = warp;
    if (shifted) {
        int bi  = warp / 3136;
        int rem = warp % 3136;
        int w   = rem / 49, n = rem % 49;
        int wh = w >> 3, ww = w & 7;
        int r = n / 7, cc = n % 7;
        int sh = wh * 7 + r + 3;  if (sh >= 56) sh -= 56;
        int sw = ww * 7 + cc + 3; if (sw >= 56) sw -= 56;
        src = bi * 3136 + sh * 56 + sw;
    }
    const float* xr = x + (size_t)src * 96;
    float v0 = xr[lane], v1 = xr[lane + 32], v2 = xr[lane + 64];
    float s  = v0 + v1 + v2;
    float s2 = v0 * v0 + v1 * v1 + v2 * v2;
    #pragma unroll
    for (int o = 16; o; o >>= 1) {
        s  += __shfl_xor_sync(0xffffffffu, s,  o);
        s2 += __shfl_xor_sync(0xffffffffu, s2, o);
    }
    float mean = s * (1.0f / 96.0f);
    float var  = s2 * (1.0f / 96.0f) - mean * mean;
    float rs   = rsqrtf(var + 1e-5f);
    __nv_bfloat16* orow = out + (size_t)warp * 96;
    orow[lane]      = __float2bfloat16((v0 - mean) * rs * g[lane]      + b[lane]);
    orow[lane + 32] = __float2bfloat16((v1 - mean) * rs * g[lane + 32] + b[lane + 32]);
    orow[lane + 64] = __float2bfloat16((v2 - mean) * rs * g[lane + 64] + b[lane + 64]);
}

// ---------------------------------------------------------------------------
// Pipelined HMMA GEMM (unchanged from R4)
// ---------------------------------------------------------------------------
template <int MODE, int KGLOB, int KCH, int NOUT, int TILES>
__global__ void __launch_bounds__(256)
tc_gemm(const __nv_bfloat16* __restrict__ A, const __nv_bfloat16* __restrict__ Wb,
        const float* __restrict__ bias, void* __restrict__ outv,
        const float* __restrict__ resid) {
    constexpr bool BRES = (KCH == 1);
    constexpr int ABYTES = 128 * 104 * 2;
    constexpr int BBYTES = 96 * 104 * 2;
    extern __shared__ char smem[];
    const uint32_t sbase = smem_u32(smem);
    const uint32_t Ab0 = sbase, Ab1 = sbase + ABYTES;
    const uint32_t Bb0 = sbase + 2 * ABYTES;
    const uint32_t Bb1 = BRES ? Bb0 : Bb0 + BBYTES;

    const int tid   = threadIdx.x;
    const int lane  = tid & 31;
    const int wid   = tid >> 5;
    const int wm    = wid & 3;
    const int wn    = wid >> 2;
    const int nb    = blockIdx.y;
    const int tile0 = blockIdx.x * TILES;
    const int NSTEP = TILES * KCH;

    auto issueA = [&](int s) {
        int tile = s / KCH, kc = s % KCH;
        const __nv_bfloat16* src = A + (size_t)(tile0 + tile) * 128 * KGLOB + kc * 96;
        uint32_t dst = (s & 1) ? Ab1 : Ab0;
        #pragma unroll
        for (int i = tid; i < 128 * 24; i += 256) {
            int r = i / 24, c = i % 24;
            cp8(dst + r * 208 + c * 8, src + (size_t)r * KGLOB + c * 4);
        }
    };
    auto issueB = [&](int s) {
        int kc = s % KCH;
        const __nv_bfloat16* src = Wb + (size_t)nb * 96 * KGLOB + kc * 96;
        uint32_t dst = (s & 1) ? Bb1 : Bb0;
        #pragma unroll
        for (int i = tid; i < 96 * 24; i += 256) {
            int r = i / 24, c = i % 24;
            cp8(dst + r * 208 + c * 8, src + (size_t)r * KGLOB + c * 4);
        }
    };

    issueA(0); issueB(0); CP_COMMIT();

    float acc[2][6][4];

    for (int s = 0; s < NSTEP; s++) {
        const int kc = s % KCH, tile = s / KCH;
        const bool hasnext = (s + 1 < NSTEP);
        if (hasnext) {
            issueA(s + 1);
            if (!BRES) issueB(s + 1);
            CP_COMMIT();
            asm volatile("cp.async.wait_group 1;" ::: "memory");
        } else {
            asm volatile("cp.async.wait_group 0;" ::: "memory");
        }
        __syncthreads();

        if (kc == 0) {
            #pragma unroll
            for (int m = 0; m < 2; m++)
                #pragma unroll
                for (int n = 0; n < 6; n++)
                    #pragma unroll
                    for (int v = 0; v < 4; v++) acc[m][n][v] = 0.0f;
        }

        const uint32_t abase = (s & 1) ? Ab1 : Ab0;
        const uint32_t bbase = BRES ? Bb0 : ((s & 1) ? Bb1 : Bb0);

        #pragma unroll
        for (int kk = 0; kk < 6; kk++) {
            const int k = kk * 16;
            uint32_t a[2][4];
            #pragma unroll
            for (int m = 0; m < 2; m++)
                ldm_x4(a[m][0], a[m][1], a[m][2], a[m][3],
                       abase + ((uint32_t)((wm * 32 + m * 16 + (lane & 15)) * 104
                                           + k + (lane >> 4) * 8) << 1));
            #pragma unroll
            for (int g = 0; g < 3; g++) {
                uint32_t b0, b1, b2, b3;
                ldm_x4(b0, b1, b2, b3,
                       bbase + ((uint32_t)((wn * 48 + g * 16 + (lane & 15)) * 104
                                           + k + (lane >> 4) * 8) << 1));
                #pragma unroll
                for (int m = 0; m < 2; m++) {
                    mma_bf16(acc[m][g * 2],     a[m][0], a[m][1], a[m][2], a[m][3], b0, b2);
                    mma_bf16(acc[m][g * 2 + 1], a[m][0], a[m][1], a[m][2], a[m][3], b1, b3);
                }
            }
        }

        if (kc == KCH - 1) {
            const int row0 = (tile0 + tile) * 128 + wm * 32;
            const int colb = nb * 96 + wn * 48;
            #pragma unroll
            for (int m = 0; m < 2; m++) {
                const int ra = row0 + m * 16 + (lane >> 2);
                const int rb = ra + 8;
                int da = ra, db = rb;
                if (MODE == 1) {
                    #pragma unroll
                    for (int t2 = 0; t2 < 2; t2++) {
                        int row = t2 ? rb : ra;
                        int bi  = row / 3136;
                        int rem = row % 3136;
                        int ww_ = rem / 49, n = rem % 49;
                        int wh = ww_ >> 3, wcl = ww_ & 7;
                        int r7 = n / 7, c7 = n % 7;
                        int hh = wh * 7 + r7 + 3;  if (hh >= 56) hh -= 56;
                        int zz = wcl * 7 + c7 + 3; if (zz >= 56) zz -= 56;
                        int d = bi * 3136 + hh * 56 + zz;
                        if (t2) db = d; else da = d;
                    }
                }
                #pragma unroll
                for (int n = 0; n < 6; n++) {
                    const int col = colb + n * 8 + (lane & 3) * 2;
                    float bi0 = __ldg(bias + col), bi1 = __ldg(bias + col + 1);
                    float v00 = acc[m][n][0] + bi0, v01 = acc[m][n][1] + bi1;
                    float v10 = acc[m][n][2] + bi0, v11 = acc[m][n][3] + bi1;
                    if (MODE == 0) {
                        if (col < 96) { v00 *= QSCALE; v01 *= QSCALE; v10 *= QSCALE; v11 *= QSCALE; }
                        __nv_bfloat16* out = (__nv_bfloat16*)outv;
                        *reinterpret_cast<uint32_t*>(out + (size_t)ra * NOUT + col) = packbf(v00, v01);
                        *reinterpret_cast<uint32_t*>(out + (size_t)rb * NOUT + col) = packbf(v10, v11);
                    } else if (MODE == 1) {
                        float* out = (float*)outv;
                        size_t oa = (size_t)da * 96 + col, ob = (size_t)db * 96 + col;
                        float2 r0 = *reinterpret_cast<const float2*>(resid + oa);
                        float2 r1 = *reinterpret_cast<const float2*>(resid + ob);
                        float2 w0 = make_float2(r0.x + v00, r0.y + v01);
                        float2 w1 = make_float2(r1.x + v10, r1.y + v11);
                        *reinterpret_cast<float2*>(out + oa) = w0;
                        *reinterpret_cast<float2*>(out + ob) = w1;
                    } else if (MODE == 2) {
                        v00 = 0.5f * v00 * (1.0f + erff(v00 * 0.70710678118654752f));
                        v01 = 0.5f * v01 * (1.0f + erff(v01 * 0.70710678118654752f));
                        v10 = 0.5f * v10 * (1.0f + erff(v10 * 0.70710678118654752f));
                        v11 = 0.5f * v11 * (1.0f + erff(v11 * 0.70710678118654752f));
                        __nv_bfloat16* out = (__nv_bfloat16*)outv;
                        *reinterpret_cast<uint32_t*>(out + (size_t)ra * NOUT + col) = packbf(v00, v01);
                        *reinterpret_cast<uint32_t*>(out + (size_t)rb * NOUT + col) = packbf(v10, v11);
                    } else {
                        float* out = (float*)outv;
                        size_t oa = (size_t)ra * 96 + col, ob = (size_t)rb * 96 + col;
                        float2 r0 = *reinterpret_cast<const float2*>(out + oa);
                        float2 r1 = *reinterpret_cast<const float2*>(out + ob);
                        r0.x += v00; r0.y += v01; r1.x += v10; r1.y += v11;
                        *reinterpret_cast<float2*>(out + oa) = r0;
                        *reinterpret_cast<float2*>(out + ob) = r1;
                    }
                }
            }
        }
        __syncthreads();
    }
}

// ---------------------------------------------------------------------------
// Tensor-core windowed attention. Block = 1 window, 6 warps.
// Warp w: head h = w/2, row-half mh = w&1 (rows mh*32..+32, padded to 64).
// S = Q@K^T via mma; bias+mask in fragment layout; quad-shfl softmax;
// P stays in registers (C-frag == A-frag trick); P@V via mma with
// ldmatrix.trans V fragments.
// ---------------------------------------------------------------------------
__global__ void __launch_bounds__(192)
attn_tc(const __nv_bfloat16* __restrict__ qkv, const float* __restrict__ rpb,
        __nv_bfloat16* __restrict__ out) {
    extern __shared__ char ash[];
    // Q/K/V: [3 heads][64 rows][40 cols] bf16 (rows>=49 zero, cols>=32 junk-free pad)
    __nv_bfloat16* Qs = reinterpret_cast<__nv_bfloat16*>(ash);
    __nv_bfloat16* Ks = Qs + 7680;
    __nv_bfloat16* Vs = Ks + 7680;
    float*         rpbs = reinterpret_cast<float*>(Vs + 7680);   // 507
    int*           labs = reinterpret_cast<int*>(rpbs + 507);    // 49

    const uint32_t qb = smem_u32(Qs), kb = smem_u32(Ks), vb = smem_u32(Vs);
    const int wb  = blockIdx.x;
    const int t0  = wb * 49;
    const int tid = threadIdx.x;
    const int lane = tid & 31;
    const int wid  = tid >> 5;

    // ---- cooperative load: 64 rows x 144 words (q48|k48|v48) ----
    for (int idx = tid; idx < 64 * 144; idx += 192) {
        int j = idx / 144, w = idx % 144;
        int arr = w / 48, ww = w % 48;
        int h = ww / 16, d2 = ww % 16;
        uint32_t val = 0;
        if (j < 49)
            val = reinterpret_cast<const uint32_t*>(qkv + (size_t)(t0 + j) * 288)[w];
        uint32_t off = (uint32_t)(h * 2560 + j * 40 + d2 * 2);   // bf16 units (even)
        __nv_bfloat16* base = (arr == 0) ? Qs : (arr == 1) ? Ks : Vs;
        *reinterpret_cast<uint32_t*>(base + off) = val;
    }
    for (int i = tid; i < 507; i += 192) rpbs[i] = rpb[i];
    {
        const int w  = wb & 63;
        const int wh = w >> 3, ww = w & 7;
        if (tid < 49) {
            int r = tid / 7, cc = tid % 7;
            int hh = wh * 7 + r, zz = ww * 7 + cc;
            int rh = (hh < 49) ? 0 : ((hh < 53) ? 1 : 2);
            int rw = (zz < 49) ? 0 : ((zz < 53) ? 1 : 2);
            labs[tid] = rh * 3 + rw;
        }
    }
    __syncthreads();

    const int h  = wid >> 1;
    const int mh = wid & 1;
    const int rbase = mh * 32;
    const uint32_t qh = qb + (uint32_t)h * 5120;   // bytes
    const uint32_t kh = kb + (uint32_t)h * 5120;
    const uint32_t vh = vb + (uint32_t)h * 5120;

    // ---- S = Q @ K^T : c[mt][ntile][4], ntile covers j cols ntile*8..+8 ----
    float c[2][8][4];
    #pragma unroll
    for (int m = 0; m < 2; m++)
        #pragma unroll
        for (int n = 0; n < 8; n++)
            #pragma unroll
            for (int v = 0; v < 4; v++) c[m][n][v] = 0.0f;

    #pragma unroll
    for (int kk = 0; kk < 2; kk++) {
        uint32_t qa[2][4];
        #pragma unroll
        for (int mt = 0; mt < 2; mt++)
            ldm_x4(qa[mt][0], qa[mt][1], qa[mt][2], qa[mt][3],
                   qh + ((uint32_t)((rbase + mt * 16 + (lane & 15)) * 40
                                    + kk * 16 + (lane >> 4) * 8) << 1));
        #pragma unroll
        for (int np = 0; np < 4; np++) {
            uint32_t b0, b1, b2, b3;
            ldm_x4(b0, b1, b2, b3,
                   kh + ((uint32_t)((np * 16 + (lane & 15)) * 40
                                    + kk * 16 + (lane >> 4) * 8) << 1));
            #pragma unroll
            for (int mt = 0; mt < 2; mt++) {
                mma_bf16(c[mt][np * 2],     qa[mt][0], qa[mt][1], qa[mt][2], qa[mt][3], b0, b2);
                mma_bf16(c[mt][np * 2 + 1], qa[mt][0], qa[mt][1], qa[mt][2], qa[mt][3], b1, b3);
            }
        }
    }

    // ---- bias + mask + softmax in fragment layout ----
    // rows: i[mt][p] = rbase + mt*16 + (lane>>2) + p*8
    // cols: j[nt][q] = nt*8 + (lane&3)*2 + q
    int ric[2][2], cic[2][2], labi[2][2];
    #pragma unroll
    for (int mt = 0; mt < 2; mt++)
        #pragma unroll
        for (int p = 0; p < 2; p++) {
            int i  = rbase + mt * 16 + (lane >> 2) + p * 8;
            int ic = i < 49 ? i : 48;
            ric[mt][p] = ic / 7; cic[mt][p] = ic % 7; labi[mt][p] = labs[ic];
        }
    int rj[16], cj[16], labj[16], jok[16];
    #pragma unroll
    for (int nt = 0; nt < 8; nt++)
        #pragma unroll
        for (int q = 0; q < 2; q++) {
            int j  = nt * 8 + (lane & 3) * 2 + q;
            int jc = j < 49 ? j : 48;
            rj[nt * 2 + q] = jc / 7; cj[nt * 2 + q] = jc % 7;
            labj[nt * 2 + q] = labs[jc]; jok[nt * 2 + q] = (j < 49);
        }
    #pragma unroll
    for (int mt = 0; mt < 2; mt++)
        #pragma unroll
        for (int p = 0; p < 2; p++) {
            #pragma unroll
            for (int nt = 0; nt < 8; nt++)
                #pragma unroll
                for (int q = 0; q < 2; q++) {
                    int e = nt * 2 + q;
                    float v = c[mt][nt][p * 2 + q];
                    v += rpbs[((ric[mt][p] - rj[e] + 6) * 13 + (cic[mt][p] - cj[e] + 6)) * 3 + h];
                    if (labj[e] != labi[mt][p]) v -= 100.0f;
                    if (!jok[e]) v = -1e30f;
                    c[mt][nt][p * 2 + q] = v;
                }
        }
    // row max / exp / sum (quad shfl: lanes l^1, l^2 share the row)
    #pragma unroll
    for (int mt = 0; mt < 2; mt++) {
        #pragma unroll
        for (int p = 0; p < 2; p++) {
            float mx = -1e30f;
            #pragma unroll
            for (int nt = 0; nt < 8; nt++) {
                mx = fmaxf(mx, c[mt][nt][p * 2]);
                mx = fmaxf(mx, c[mt][nt][p * 2 + 1]);
            }
            mx = fmaxf(mx, __shfl_xor_sync(0xffffffffu, mx, 1));
            mx = fmaxf(mx, __shfl_xor_sync(0xffffffffu, mx, 2));
            float sum = 0.0f;
            #pragma unroll
            for (int nt = 0; nt < 8; nt++) {
                float e0 = __expf(c[mt][nt][p * 2]     - mx);
                float e1 = __expf(c[mt][nt][p * 2 + 1] - mx);
                c[mt][nt][p * 2] = e0; c[mt][nt][p * 2 + 1] = e1;
                sum += e0 + e1;
            }
            sum += __shfl_xor_sync(0xffffffffu, sum, 1);
            sum += __shfl_xor_sync(0xffffffffu, sum, 2);
            float inv = 1.0f / sum;
            #pragma unroll
            for (int nt = 0; nt < 8; nt++) {
                c[mt][nt][p * 2] *= inv; c[mt][nt][p * 2 + 1] *= inv;
            }
        }
    }

    // ---- O = P @ V : P in registers (C-frag == A-frag), V via ldmatrix.trans
    float o[2][4][4];
    #pragma unroll
    for (int m = 0; m < 2; m++)
        #pragma unroll
        for (int n = 0; n < 4; n++)
            #pragma unroll
            for (int v = 0; v < 4; v++) o[m][n][v] = 0.0f;

    #pragma unroll
    for (int kk = 0; kk < 4; kk++) {   // k = j, 16 per step
        uint32_t vf[2][4];             // d 0-15, 16-31
        #pragma unroll
        for (int dh = 0; dh < 2; dh++)
            ldm_x4t(vf[dh][0], vf[dh][1], vf[dh][2], vf[dh][3],
                    vh + ((uint32_t)((kk * 16 + (lane & 7) + ((lane >> 3) & 1) * 8) * 40
                                     + dh * 16 + (lane >> 4) * 8) << 1));
        #pragma unroll
        for (int mt = 0; mt < 2; mt++) {
            uint32_t pa0 = packbf(c[mt][2 * kk][0],     c[mt][2 * kk][1]);
            uint32_t pa1 = packbf(c[mt][2 * kk][2],     c[mt][2 * kk][3]);
            uint32_t pa2 = packbf(c[mt][2 * kk + 1][0], c[mt][2 * kk + 1][1]);
            uint32_t pa3 = packbf(c[mt][2 * kk + 1][2], c[mt][2 * kk + 1][3]);
            #pragma unroll
            for (int dn = 0; dn < 4; dn++) {
                uint32_t vb0 = (dn & 1) ? vf[dn >> 1][2] : vf[dn >> 1][0];
                uint32_t vb1 = (dn & 1) ? vf[dn >> 1][3] : vf[dn >> 1][1];
                mma_bf16(o[mt][dn], pa0, pa1, pa2, pa3, vb0, vb1);
            }
        }
    }

    // ---- store O rows < 49 ----
    #pragma unroll
    for (int mt = 0; mt < 2; mt++)
        #pragma unroll
        for (int p = 0; p < 2; p++) {
            int i = rbase + mt * 16 + (lane >> 2) + p * 8;
            if (i < 49) {
                __nv_bfloat16* orow = out + (size_t)(t0 + i) * 96 + h * 32;
                #pragma unroll
                for (int dn = 0; dn < 4; dn++) {
                    int d = dn * 8 + (lane & 3) * 2;
                    *reinterpret_cast<uint32_t*>(orow + d) =
                        packbf(o[mt][dn][p * 2], o[mt][dn][p * 2 + 1]);
                }
            }
        }
}

// ---------------------------------------------------------------------------
extern "C" void kernel_launch(void* const* d_in, const int* in_sizes, int n_in,
                              void* d_out, int out_size) {
    const float* x      = (const float*)d_in[0];
    const float* n1g    = (const float*)d_in[1];
    const float* n1b    = (const float*)d_in[2];
    const float* qkv_w  = (const float*)d_in[3];
    const float* qkv_b  = (const float*)d_in[4];
    const float* rpb    = (const float*)d_in[5];
    const float* proj_w = (const float*)d_in[6];
    const float* proj_b = (const float*)d_in[7];
    const float* n2g    = (const float*)d_in[8];
    const float* n2b    = (const float*)d_in[9];
    const float* fc1_w  = (const float*)d_in[10];
    const float* fc1_b  = (const float*)d_in[11];
    const float* fc2_w  = (const float*)d_in[12];
    const float* fc2_b  = (const float*)d_in[13];
    float* out = (float*)d_out;

    __nv_bfloat16 *buf1, *buf2, *wb;
    cudaGetSymbolAddress((void**)&buf1, g_buf1);
    cudaGetSymbolAddress((void**)&buf2, g_buf2);
    cudaGetSymbolAddress((void**)&wb,   g_wbuf);

    const int smem_k96  = 2 * 26624 + 19968;
    const int smem_k384 = 2 * 26624 + 2 * 19968;
    const int smem_attn = 3 * 7680 * 2 + 507 * 4 + 49 * 4 + 16;   // ~48.3 KB
    cudaFuncSetAttribute(tc_gemm<0, 96, 1, 288, 8>,   cudaFuncAttributeMaxDynamicSharedMemorySize, smem_k96);
    cudaFuncSetAttribute(tc_gemm<1, 96, 1, 96, 4>,    cudaFuncAttributeMaxDynamicSharedMemorySize, smem_k96);
    cudaFuncSetAttribute(tc_gemm<2, 96, 1, 384, 16>,  cudaFuncAttributeMaxDynamicSharedMemorySize, smem_k96);
    cudaFuncSetAttribute(tc_gemm<3, 384, 4, 96, 4>,   cudaFuncAttributeMaxDynamicSharedMemorySize, smem_k384);
    cudaFuncSetAttribute(attn_tc, cudaFuncAttributeMaxDynamicSharedMemorySize, smem_attn);

    // 0) weights fp32 -> bf16
    wconv<<<432, 256>>>(qkv_w, proj_w, fc1_w, fc2_w, wb);
    // 1) LN1 + shift + window partition -> buf2 bf16 [T,96]
    ln_kernel<<<TKN / 8, 256>>>(x, n1g, n1b, buf2, 1);
    // 2) QKV GEMM (q pre-scaled) -> buf1 bf16 [T,288]
    tc_gemm<0, 96, 1, 288, 8><<<dim3(196, 3), 256, smem_k96>>>(buf2, wb + WOFF_QKV, qkv_b, buf1, nullptr);
    // 3) tensor-core windowed attention -> buf2 bf16 [T,96]
    attn_tc<<<4096, 192, smem_attn>>>(buf1, rpb, buf2);
    // 4) proj GEMM + window reverse + unshift + residual -> d_out fp32 [T,96]
    tc_gemm<1, 96, 1, 96, 4><<<dim3(392, 1), 256, smem_k96>>>(buf2, wb + WOFF_PROJ, proj_b, out, x);
    // 5) LN2 -> buf2 bf16 [T,96]
    ln_kernel<<<TKN / 8, 256>>>(out, n2g, n2b, buf2, 0);
    // 6) FC1 + GELU -> buf1 bf16 [T,384]
    tc_gemm<2, 96, 1, 384, 16><<<dim3(98, 4), 256, smem_k96>>>(buf2, wb + WOFF_FC1, fc1_b, buf1, nullptr);
    // 7) FC2 + accumulate into d_out
    tc_gemm<3, 384, 4, 96, 4><<<dim3(392, 1), 256, smem_k384>>>(buf1, wb + WOFF_FC2, fc2_b, out, nullptr);
}

// round 6
// speedup vs baseline: 4.4600x; 1.0578x over previous
#include <cuda_runtime.h>
#include <cuda_bf16.h>
#include <math.h>
#include <cstdint>

#define TKN    200704
#define QSCALE 0.17677669529663688f

// Scratch (allocation-free): bf16 activations + pre-converted weights
__device__ __nv_bfloat16 g_buf1[200704 * 384];  // qkv [T,288] then fc1-out [T,384]
__device__ __nv_bfloat16 g_buf2[200704 * 96];   // ln1-out, attn-out, ln2-out [T,96]
__device__ __nv_bfloat16 g_wbuf[110592];        // qkv_w | proj_w | fc1_w | fc2_w (bf16)
__device__ __nv_bfloat16 g_bias[4 * 3 * 64 * 64]; // combined bias+mask per window class

#define WOFF_QKV  0
#define WOFF_PROJ 27648
#define WOFF_FC1  36864
#define WOFF_FC2  73728

// ---------------------------------------------------------------------------
// PTX helpers
// ---------------------------------------------------------------------------
__device__ __forceinline__ uint32_t smem_u32(const void* p) {
    uint32_t a;
    asm("{ .reg .u64 t; cvta.to.shared.u64 t, %1; cvt.u32.u64 %0, t; }" : "=r"(a) : "l"(p));
    return a;
}
__device__ __forceinline__ void cp8(uint32_t dst, const void* src) {
    asm volatile("cp.async.ca.shared.global [%0], [%1], 8;" :: "r"(dst), "l"(src));
}
#define CP_COMMIT() asm volatile("cp.async.commit_group;" ::: "memory")
__device__ __forceinline__ void ldm_x4(uint32_t& r0, uint32_t& r1, uint32_t& r2, uint32_t& r3,
                                       uint32_t addr) {
    asm volatile("ldmatrix.sync.aligned.m8n8.x4.shared.b16 {%0,%1,%2,%3}, [%4];"
                 : "=r"(r0), "=r"(r1), "=r"(r2), "=r"(r3) : "r"(addr));
}
__device__ __forceinline__ void ldm_x4t(uint32_t& r0, uint32_t& r1, uint32_t& r2, uint32_t& r3,
                                        uint32_t addr) {
    asm volatile("ldmatrix.sync.aligned.m8n8.x4.trans.shared.b16 {%0,%1,%2,%3}, [%4];"
                 : "=r"(r0), "=r"(r1), "=r"(r2), "=r"(r3) : "r"(addr));
}
__device__ __forceinline__ void mma_bf16(float* c, uint32_t a0, uint32_t a1, uint32_t a2,
                                         uint32_t a3, uint32_t b0, uint32_t b1) {
    asm volatile("mma.sync.aligned.m16n8k16.row.col.f32.bf16.bf16.f32 "
                 "{%0,%1,%2,%3}, {%4,%5,%6,%7}, {%8,%9}, {%0,%1,%2,%3};"
                 : "+f"(c[0]), "+f"(c[1]), "+f"(c[2]), "+f"(c[3])
                 : "r"(a0), "r"(a1), "r"(a2), "r"(a3), "r"(b0), "r"(b1));
}
__device__ __forceinline__ uint32_t packbf(float a, float b) {
    __nv_bfloat162 h = __floats2bfloat162_rn(a, b);
    return *reinterpret_cast<uint32_t*>(&h);
}

// ---------------------------------------------------------------------------
// Weight pre-convert fp32 -> bf16
// ---------------------------------------------------------------------------
__global__ void wconv(const float* __restrict__ a, const float* __restrict__ b,
                      const float* __restrict__ c, const float* __restrict__ d,
                      __nv_bfloat16* __restrict__ o) {
    int i = blockIdx.x * 256 + threadIdx.x;
    if (i < 27648)       o[i] = __float2bfloat16(a[i]);
    else if (i < 36864)  o[i] = __float2bfloat16(b[i - 27648]);
    else if (i < 73728)  o[i] = __float2bfloat16(c[i - 36864]);
    else if (i < 110592) o[i] = __float2bfloat16(d[i - 73728]);
}

// ---------------------------------------------------------------------------
// Combined bias table: tab[cls][h][i(64)][j(64)] = rpb + shiftmask, j>=49 -> -1e30
// cls = (wh==7)*2 + (ww==7)
// ---------------------------------------------------------------------------
__device__ __forceinline__ int winlab(int cls, int r, int c) {
    int rh = (cls & 2) ? (r < 4 ? 1 : 2) : 0;
    int rw = (cls & 1) ? (c < 4 ? 1 : 2) : 0;
    return rh * 3 + rw;
}
__global__ void bias_prep(const float* __restrict__ rpb, __nv_bfloat16* __restrict__ tab) {
    int idx = blockIdx.x * 256 + threadIdx.x;
    if (idx >= 4 * 3 * 64 * 64) return;
    int j = idx & 63, i = (idx >> 6) & 63;
    int h = (idx >> 12) % 3, cls = idx >> 12; cls /= 3;
    float v;
    if (j >= 49 || i >= 49) v = -1e30f;
    else {
        int ri = i / 7, ci = i % 7, rj = j / 7, cj = j % 7;
        v = rpb[((ri - rj + 6) * 13 + (ci - cj + 6)) * 3 + h];
        if (winlab(cls, ri, ci) != winlab(cls, rj, cj)) v -= 100.0f;
    }
    tab[idx] = __float2bfloat16(v);
}

// ---------------------------------------------------------------------------
// LN kernel (one warp per token, bf16 out, optional shift+partition gather)
// ---------------------------------------------------------------------------
__global__ void ln_kernel(const float* __restrict__ x, const float* __restrict__ g,
                          const float* __restrict__ b, __nv_bfloat16* __restrict__ out,
                          int shifted) {
    int warp = (blockIdx.x * blockDim.x + threadIdx.x) >> 5;
    int lane = threadIdx.x & 31;
    if (warp >= TKN) return;
    int src = warp;
    if (shifted) {
        int bi  = warp / 3136;
        int rem = warp % 3136;
        int w   = rem / 49, n = rem % 49;
        int wh = w >> 3, ww = w & 7;
        int r = n / 7, cc = n % 7;
        int sh = wh * 7 + r + 3;  if (sh >= 56) sh -= 56;
        int sw = ww * 7 + cc + 3; if (sw >= 56) sw -= 56;
        src = bi * 3136 + sh * 56 + sw;
    }
    const float* xr = x + (size_t)src * 96;
    float v0 = xr[lane], v1 = xr[lane + 32], v2 = xr[lane + 64];
    float s  = v0 + v1 + v2;
    float s2 = v0 * v0 + v1 * v1 + v2 * v2;
    #pragma unroll
    for (int o = 16; o; o >>= 1) {
        s  += __shfl_xor_sync(0xffffffffu, s,  o);
        s2 += __shfl_xor_sync(0xffffffffu, s2, o);
    }
    float mean = s * (1.0f / 96.0f);
    float var  = s2 * (1.0f / 96.0f) - mean * mean;
    float rs   = rsqrtf(var + 1e-5f);
    __nv_bfloat16* orow = out + (size_t)warp * 96;
    orow[lane]      = __float2bfloat16((v0 - mean) * rs * g[lane]      + b[lane]);
    orow[lane + 32] = __float2bfloat16((v1 - mean) * rs * g[lane + 32] + b[lane + 32]);
    orow[lane + 64] = __float2bfloat16((v2 - mean) * rs * g[lane + 64] + b[lane + 64]);
}

// ---------------------------------------------------------------------------
// Pipelined HMMA GEMM (unchanged)
// ---------------------------------------------------------------------------
template <int MODE, int KGLOB, int KCH, int NOUT, int TILES>
__global__ void __launch_bounds__(256)
tc_gemm(const __nv_bfloat16* __restrict__ A, const __nv_bfloat16* __restrict__ Wb,
        const float* __restrict__ bias, void* __restrict__ outv,
        const float* __restrict__ resid) {
    constexpr bool BRES = (KCH == 1);
    constexpr int ABYTES = 128 * 104 * 2;
    constexpr int BBYTES = 96 * 104 * 2;
    extern __shared__ char smem[];
    const uint32_t sbase = smem_u32(smem);
    const uint32_t Ab0 = sbase, Ab1 = sbase + ABYTES;
    const uint32_t Bb0 = sbase + 2 * ABYTES;
    const uint32_t Bb1 = BRES ? Bb0 : Bb0 + BBYTES;

    const int tid   = threadIdx.x;
    const int lane  = tid & 31;
    const int wid   = tid >> 5;
    const int wm    = wid & 3;
    const int wn    = wid >> 2;
    const int nb    = blockIdx.y;
    const int tile0 = blockIdx.x * TILES;
    const int NSTEP = TILES * KCH;

    auto issueA = [&](int s) {
        int tile = s / KCH, kc = s % KCH;
        const __nv_bfloat16* src = A + (size_t)(tile0 + tile) * 128 * KGLOB + kc * 96;
        uint32_t dst = (s & 1) ? Ab1 : Ab0;
        #pragma unroll
        for (int i = tid; i < 128 * 24; i += 256) {
            int r = i / 24, c = i % 24;
            cp8(dst + r * 208 + c * 8, src + (size_t)r * KGLOB + c * 4);
        }
    };
    auto issueB = [&](int s) {
        int kc = s % KCH;
        const __nv_bfloat16* src = Wb + (size_t)nb * 96 * KGLOB + kc * 96;
        uint32_t dst = (s & 1) ? Bb1 : Bb0;
        #pragma unroll
        for (int i = tid; i < 96 * 24; i += 256) {
            int r = i / 24, c = i % 24;
            cp8(dst + r * 208 + c * 8, src + (size_t)r * KGLOB + c * 4);
        }
    };

    issueA(0); issueB(0); CP_COMMIT();

    float acc[2][6][4];

    for (int s = 0; s < NSTEP; s++) {
        const int kc = s % KCH, tile = s / KCH;
        const bool hasnext = (s + 1 < NSTEP);
        if (hasnext) {
            issueA(s + 1);
            if (!BRES) issueB(s + 1);
            CP_COMMIT();
            asm volatile("cp.async.wait_group 1;" ::: "memory");
        } else {
            asm volatile("cp.async.wait_group 0;" ::: "memory");
        }
        __syncthreads();

        if (kc == 0) {
            #pragma unroll
            for (int m = 0; m < 2; m++)
                #pragma unroll
                for (int n = 0; n < 6; n++)
                    #pragma unroll
                    for (int v = 0; v < 4; v++) acc[m][n][v] = 0.0f;
        }

        const uint32_t abase = (s & 1) ? Ab1 : Ab0;
        const uint32_t bbase = BRES ? Bb0 : ((s & 1) ? Bb1 : Bb0);

        #pragma unroll
        for (int kk = 0; kk < 6; kk++) {
            const int k = kk * 16;
            uint32_t a[2][4];
            #pragma unroll
            for (int m = 0; m < 2; m++)
                ldm_x4(a[m][0], a[m][1], a[m][2], a[m][3],
                       abase + ((uint32_t)((wm * 32 + m * 16 + (lane & 15)) * 104
                                           + k + (lane >> 4) * 8) << 1));
            #pragma unroll
            for (int g = 0; g < 3; g++) {
                uint32_t b0, b1, b2, b3;
                ldm_x4(b0, b1, b2, b3,
                       bbase + ((uint32_t)((wn * 48 + g * 16 + (lane & 15)) * 104
                                           + k + (lane >> 4) * 8) << 1));
                #pragma unroll
                for (int m = 0; m < 2; m++) {
                    mma_bf16(acc[m][g * 2],     a[m][0], a[m][1], a[m][2], a[m][3], b0, b2);
                    mma_bf16(acc[m][g * 2 + 1], a[m][0], a[m][1], a[m][2], a[m][3], b1, b3);
                }
            }
        }

        if (kc == KCH - 1) {
            const int row0 = (tile0 + tile) * 128 + wm * 32;
            const int colb = nb * 96 + wn * 48;
            #pragma unroll
            for (int m = 0; m < 2; m++) {
                const int ra = row0 + m * 16 + (lane >> 2);
                const int rb = ra + 8;
                int da = ra, db = rb;
                if (MODE == 1) {
                    #pragma unroll
                    for (int t2 = 0; t2 < 2; t2++) {
                        int row = t2 ? rb : ra;
                        int bi  = row / 3136;
                        int rem = row % 3136;
                        int ww_ = rem / 49, n = rem % 49;
                        int wh = ww_ >> 3, wcl = ww_ & 7;
                        int r7 = n / 7, c7 = n % 7;
                        int hh = wh * 7 + r7 + 3;  if (hh >= 56) hh -= 56;
                        int zz = wcl * 7 + c7 + 3; if (zz >= 56) zz -= 56;
                        int d = bi * 3136 + hh * 56 + zz;
                        if (t2) db = d; else da = d;
                    }
                }
                #pragma unroll
                for (int n = 0; n < 6; n++) {
                    const int col = colb + n * 8 + (lane & 3) * 2;
                    float bi0 = __ldg(bias + col), bi1 = __ldg(bias + col + 1);
                    float v00 = acc[m][n][0] + bi0, v01 = acc[m][n][1] + bi1;
                    float v10 = acc[m][n][2] + bi0, v11 = acc[m][n][3] + bi1;
                    if (MODE == 0) {
                        if (col < 96) { v00 *= QSCALE; v01 *= QSCALE; v10 *= QSCALE; v11 *= QSCALE; }
                        __nv_bfloat16* out = (__nv_bfloat16*)outv;
                        *reinterpret_cast<uint32_t*>(out + (size_t)ra * NOUT + col) = packbf(v00, v01);
                        *reinterpret_cast<uint32_t*>(out + (size_t)rb * NOUT + col) = packbf(v10, v11);
                    } else if (MODE == 1) {
                        float* out = (float*)outv;
                        size_t oa = (size_t)da * 96 + col, ob = (size_t)db * 96 + col;
                        float2 r0 = *reinterpret_cast<const float2*>(resid + oa);
                        float2 r1 = *reinterpret_cast<const float2*>(resid + ob);
                        float2 w0 = make_float2(r0.x + v00, r0.y + v01);
                        float2 w1 = make_float2(r1.x + v10, r1.y + v11);
                        *reinterpret_cast<float2*>(out + oa) = w0;
                        *reinterpret_cast<float2*>(out + ob) = w1;
                    } else if (MODE == 2) {
                        v00 = 0.5f * v00 * (1.0f + erff(v00 * 0.70710678118654752f));
                        v01 = 0.5f * v01 * (1.0f + erff(v01 * 0.70710678118654752f));
                        v10 = 0.5f * v10 * (1.0f + erff(v10 * 0.70710678118654752f));
                        v11 = 0.5f * v11 * (1.0f + erff(v11 * 0.70710678118654752f));
                        __nv_bfloat16* out = (__nv_bfloat16*)outv;
                        *reinterpret_cast<uint32_t*>(out + (size_t)ra * NOUT + col) = packbf(v00, v01);
                        *reinterpret_cast<uint32_t*>(out + (size_t)rb * NOUT + col) = packbf(v10, v11);
                    } else {
                        float* out = (float*)outv;
                        size_t oa = (size_t)ra * 96 + col, ob = (size_t)rb * 96 + col;
                        float2 r0 = *reinterpret_cast<const float2*>(out + oa);
                        float2 r1 = *reinterpret_cast<const float2*>(out + ob);
                        r0.x += v00; r0.y += v01; r1.x += v10; r1.y += v11;
                        *reinterpret_cast<float2*>(out + oa) = r0;
                        *reinterpret_cast<float2*>(out + ob) = r1;
                    }
                }
            }
        }
        __syncthreads();
    }
}

// ---------------------------------------------------------------------------
// Tensor-core windowed attention v2. Block = 1 window, 6 warps.
// Warp w: head h = w/2, row-half mh = w&1. m-tiles (16 rows) serialized to
// halve live registers. Bias+mask via precomputed per-class table (LDG).
// ---------------------------------------------------------------------------
__global__ void __launch_bounds__(192)
attn_tc(const __nv_bfloat16* __restrict__ qkv, const __nv_bfloat16* __restrict__ btab,
        __nv_bfloat16* __restrict__ out) {
    extern __shared__ char ash[];
    __nv_bfloat16* Qs = reinterpret_cast<__nv_bfloat16*>(ash);
    __nv_bfloat16* Ks = Qs + 7680;
    __nv_bfloat16* Vs = Ks + 7680;

    const uint32_t qb = smem_u32(Qs), kb = smem_u32(Ks), vb = smem_u32(Vs);
    const int wb  = blockIdx.x;
    const int t0  = wb * 49;
    const int tid = threadIdx.x;
    const int lane = tid & 31;
    const int wid  = tid >> 5;

    // cooperative load: 64 rows x 144 words (q48|k48|v48), [h][64][40] layout
    for (int idx = tid; idx < 64 * 144; idx += 192) {
        int j = idx / 144, w = idx % 144;
        int arr = w / 48, ww = w % 48;
        int h = ww / 16, d2 = ww % 16;
        uint32_t val = 0;
        if (j < 49)
            val = reinterpret_cast<const uint32_t*>(qkv + (size_t)(t0 + j) * 288)[w];
        uint32_t off = (uint32_t)(h * 2560 + j * 40 + d2 * 2);
        __nv_bfloat16* base = (arr == 0) ? Qs : (arr == 1) ? Ks : Vs;
        *reinterpret_cast<uint32_t*>(base + off) = val;
    }
    __syncthreads();

    const int h  = wid >> 1;
    const int mh = wid & 1;
    const uint32_t qh = qb + (uint32_t)h * 5120;
    const uint32_t kh = kb + (uint32_t)h * 5120;
    const uint32_t vh = vb + (uint32_t)h * 5120;

    const int w_   = wb & 63;
    const int cls  = ((w_ >> 3) == 7 ? 2 : 0) | ((w_ & 7) == 7 ? 1 : 0);
    const __nv_bfloat16* bt = btab + ((size_t)(cls * 3 + h) << 12);

    #pragma unroll
    for (int mt = 0; mt < 2; mt++) {
        const int rbase = mh * 32 + mt * 16;

        // ---- S = Q @ K^T ----
        float c[8][4];
        #pragma unroll
        for (int n = 0; n < 8; n++)
            #pragma unroll
            for (int v = 0; v < 4; v++) c[n][v] = 0.0f;

        #pragma unroll
        for (int kk = 0; kk < 2; kk++) {
            uint32_t qa0, qa1, qa2, qa3;
            ldm_x4(qa0, qa1, qa2, qa3,
                   qh + ((uint32_t)((rbase + (lane & 15)) * 40 + kk * 16 + (lane >> 4) * 8) << 1));
            #pragma unroll
            for (int np = 0; np < 4; np++) {
                uint32_t b0, b1, b2, b3;
                ldm_x4(b0, b1, b2, b3,
                       kh + ((uint32_t)((np * 16 + (lane & 15)) * 40 + kk * 16 + (lane >> 4) * 8) << 1));
                mma_bf16(c[np * 2],     qa0, qa1, qa2, qa3, b0, b2);
                mma_bf16(c[np * 2 + 1], qa0, qa1, qa2, qa3, b1, b3);
            }
        }

        // ---- bias + mask from table ----
        const int i0 = rbase + (lane >> 2);
        const uint32_t* br0 = reinterpret_cast<const uint32_t*>(bt + i0 * 64) + (lane & 3);
        const uint32_t* br1 = reinterpret_cast<const uint32_t*>(bt + (i0 + 8) * 64) + (lane & 3);
        #pragma unroll
        for (int nt = 0; nt < 8; nt++) {
            uint32_t w0 = __ldg(br0 + nt * 4);
            uint32_t w1 = __ldg(br1 + nt * 4);
            float2 f0 = __bfloat1622float2(*reinterpret_cast<__nv_bfloat162*>(&w0));
            float2 f1 = __bfloat1622float2(*reinterpret_cast<__nv_bfloat162*>(&w1));
            c[nt][0] += f0.x; c[nt][1] += f0.y;
            c[nt][2] += f1.x; c[nt][3] += f1.y;
        }

        // ---- softmax (quad shfl over lanes ^1, ^2) ----
        #pragma unroll
        for (int p = 0; p < 2; p++) {
            float mx = -1e30f;
            #pragma unroll
            for (int nt = 0; nt < 8; nt++) {
                mx = fmaxf(mx, c[nt][p * 2]);
                mx = fmaxf(mx, c[nt][p * 2 + 1]);
            }
            mx = fmaxf(mx, __shfl_xor_sync(0xffffffffu, mx, 1));
            mx = fmaxf(mx, __shfl_xor_sync(0xffffffffu, mx, 2));
            float sum = 0.0f;
            #pragma unroll
            for (int nt = 0; nt < 8; nt++) {
                float e0 = __expf(c[nt][p * 2]     - mx);
                float e1 = __expf(c[nt][p * 2 + 1] - mx);
                c[nt][p * 2] = e0; c[nt][p * 2 + 1] = e1;
                sum += e0 + e1;
            }
            sum += __shfl_xor_sync(0xffffffffu, sum, 1);
            sum += __shfl_xor_sync(0xffffffffu, sum, 2);
            float inv = 1.0f / sum;
            #pragma unroll
            for (int nt = 0; nt < 8; nt++) {
                c[nt][p * 2] *= inv; c[nt][p * 2 + 1] *= inv;
            }
        }

        // ---- O = P @ V (P in registers; V via ldmatrix.trans) ----
        float o[4][4];
        #pragma unroll
        for (int n = 0; n < 4; n++)
            #pragma unroll
            for (int v = 0; v < 4; v++) o[n][v] = 0.0f;

        #pragma unroll
        for (int kk = 0; kk < 4; kk++) {
            uint32_t vf[2][4];
            #pragma unroll
            for (int dh = 0; dh < 2; dh++)
                ldm_x4t(vf[dh][0], vf[dh][1], vf[dh][2], vf[dh][3],
                        vh + ((uint32_t)((kk * 16 + (lane & 7) + ((lane >> 3) & 1) * 8) * 40
                                         + dh * 16 + (lane >> 4) * 8) << 1));
            uint32_t pa0 = packbf(c[2 * kk][0],     c[2 * kk][1]);
            uint32_t pa1 = packbf(c[2 * kk][2],     c[2 * kk][3]);
            uint32_t pa2 = packbf(c[2 * kk + 1][0], c[2 * kk + 1][1]);
            uint32_t pa3 = packbf(c[2 * kk + 1][2], c[2 * kk + 1][3]);
            #pragma unroll
            for (int dn = 0; dn < 4; dn++) {
                uint32_t vb0 = (dn & 1) ? vf[dn >> 1][2] : vf[dn >> 1][0];
                uint32_t vb1 = (dn & 1) ? vf[dn >> 1][3] : vf[dn >> 1][1];
                mma_bf16(o[dn], pa0, pa1, pa2, pa3, vb0, vb1);
            }
        }

        // ---- store rows < 49 ----
        #pragma unroll
        for (int p = 0; p < 2; p++) {
            int i = rbase + (lane >> 2) + p * 8;
            if (i < 49) {
                __nv_bfloat16* orow = out + (size_t)(t0 + i) * 96 + h * 32;
                #pragma unroll
                for (int dn = 0; dn < 4; dn++) {
                    int d = dn * 8 + (lane & 3) * 2;
                    *reinterpret_cast<uint32_t*>(orow + d) = packbf(o[dn][p * 2], o[dn][p * 2 + 1]);
                }
            }
        }
    }
}

// ---------------------------------------------------------------------------
extern "C" void kernel_launch(void* const* d_in, const int* in_sizes, int n_in,
                              void* d_out, int out_size) {
    const float* x      = (const float*)d_in[0];
    const float* n1g    = (const float*)d_in[1];
    const float* n1b    = (const float*)d_in[2];
    const float* qkv_w  = (const float*)d_in[3];
    const float* qkv_b  = (const float*)d_in[4];
    const float* rpb    = (const float*)d_in[5];
    const float* proj_w = (const float*)d_in[6];
    const float* proj_b = (const float*)d_in[7];
    const float* n2g    = (const float*)d_in[8];
    const float* n2b    = (const float*)d_in[9];
    const float* fc1_w  = (const float*)d_in[10];
    const float* fc1_b  = (const float*)d_in[11];
    const float* fc2_w  = (const float*)d_in[12];
    const float* fc2_b  = (const float*)d_in[13];
    float* out = (float*)d_out;

    __nv_bfloat16 *buf1, *buf2, *wb, *bt;
    cudaGetSymbolAddress((void**)&buf1, g_buf1);
    cudaGetSymbolAddress((void**)&buf2, g_buf2);
    cudaGetSymbolAddress((void**)&wb,   g_wbuf);
    cudaGetSymbolAddress((void**)&bt,   g_bias);

    const int smem_k96  = 2 * 26624 + 19968;
    const int smem_k384 = 2 * 26624 + 2 * 19968;
    const int smem_attn = 3 * 7680 * 2;   // 46080
    cudaFuncSetAttribute(tc_gemm<0, 96, 1, 288, 8>,   cudaFuncAttributeMaxDynamicSharedMemorySize, smem_k96);
    cudaFuncSetAttribute(tc_gemm<1, 96, 1, 96, 4>,    cudaFuncAttributeMaxDynamicSharedMemorySize, smem_k96);
    cudaFuncSetAttribute(tc_gemm<2, 96, 1, 384, 16>,  cudaFuncAttributeMaxDynamicSharedMemorySize, smem_k96);
    cudaFuncSetAttribute(tc_gemm<3, 384, 4, 96, 4>,   cudaFuncAttributeMaxDynamicSharedMemorySize, smem_k384);
    cudaFuncSetAttribute(attn_tc, cudaFuncAttributeMaxDynamicSharedMemorySize, smem_attn);

    // 0) weights fp32 -> bf16; combined bias table
    wconv<<<432, 256>>>(qkv_w, proj_w, fc1_w, fc2_w, wb);
    bias_prep<<<192, 256>>>(rpb, bt);
    // 1) LN1 + shift + window partition -> buf2 bf16 [T,96]
    ln_kernel<<<TKN / 8, 256>>>(x, n1g, n1b, buf2, 1);
    // 2) QKV GEMM (q pre-scaled) -> buf1 bf16 [T,288]
    tc_gemm<0, 96, 1, 288, 8><<<dim3(196, 3), 256, smem_k96>>>(buf2, wb + WOFF_QKV, qkv_b, buf1, nullptr);
    // 3) tensor-core windowed attention -> buf2 bf16 [T,96]
    attn_tc<<<4096, 192, smem_attn>>>(buf1, bt, buf2);
    // 4) proj GEMM + window reverse + unshift + residual -> d_out fp32 [T,96]
    tc_gemm<1, 96, 1, 96, 4><<<dim3(392, 1), 256, smem_k96>>>(buf2, wb + WOFF_PROJ, proj_b, out, x);
    // 5) LN2 -> buf2 bf16 [T,96]
    ln_kernel<<<TKN / 8, 256>>>(out, n2g, n2b, buf2, 0);
    // 6) FC1 + GELU -> buf1 bf16 [T,384]
    tc_gemm<2, 96, 1, 384, 16><<<dim3(98, 4), 256, smem_k96>>>(buf2, wb + WOFF_FC1, fc1_b, buf1, nullptr);
    // 7) FC2 + accumulate into d_out
    tc_gemm<3, 384, 4, 96, 4><<<dim3(392, 1), 256, smem_k384>>>(buf1, wb + WOFF_FC2, fc2_b, out, nullptr);
}

// round 8
// speedup vs baseline: 4.6620x; 1.0453x over previous
#include <cuda_runtime.h>
#include <cuda_bf16.h>
#include <math.h>
#include <cstdint>

#define TKN    200704
#define QSCALE 0.17677669529663688f

// Scratch (allocation-free): bf16 activations + pre-converted weights
__device__ __nv_bfloat16 g_buf1[200704 * 384];  // qkv [T,288] then fc1-out [T,384]
__device__ __nv_bfloat16 g_buf2[200704 * 96];   // ln1-out, attn-out [T,96]
__device__ __nv_bfloat16 g_buf3[200704 * 96];   // fused-LN2 out [T,96]
__device__ __nv_bfloat16 g_wbuf[110592];        // qkv_w | proj_w | fc1_w | fc2_w (bf16)
__device__ __nv_bfloat16 g_bias[4 * 3 * 64 * 64]; // combined bias+mask per window class

#define WOFF_QKV  0
#define WOFF_PROJ 27648
#define WOFF_FC1  36864
#define WOFF_FC2  73728

// ---------------------------------------------------------------------------
// PTX helpers
// ---------------------------------------------------------------------------
__device__ __forceinline__ uint32_t smem_u32(const void* p) {
    uint32_t a;
    asm("{ .reg .u64 t; cvta.to.shared.u64 t, %1; cvt.u32.u64 %0, t; }" : "=r"(a) : "l"(p));
    return a;
}
__device__ __forceinline__ void cp8(uint32_t dst, const void* src) {
    asm volatile("cp.async.ca.shared.global [%0], [%1], 8;" :: "r"(dst), "l"(src));
}
#define CP_COMMIT() asm volatile("cp.async.commit_group;" ::: "memory")
__device__ __forceinline__ void ldm_x4(uint32_t& r0, uint32_t& r1, uint32_t& r2, uint32_t& r3,
                                       uint32_t addr) {
    asm volatile("ldmatrix.sync.aligned.m8n8.x4.shared.b16 {%0,%1,%2,%3}, [%4];"
                 : "=r"(r0), "=r"(r1), "=r"(r2), "=r"(r3) : "r"(addr));
}
__device__ __forceinline__ void ldm_x4t(uint32_t& r0, uint32_t& r1, uint32_t& r2, uint32_t& r3,
                                        uint32_t addr) {
    asm volatile("ldmatrix.sync.aligned.m8n8.x4.trans.shared.b16 {%0,%1,%2,%3}, [%4];"
                 : "=r"(r0), "=r"(r1), "=r"(r2), "=r"(r3) : "r"(addr));
}
__device__ __forceinline__ void mma_bf16(float* c, uint32_t a0, uint32_t a1, uint32_t a2,
                                         uint32_t a3, uint32_t b0, uint32_t b1) {
    asm volatile("mma.sync.aligned.m16n8k16.row.col.f32.bf16.bf16.f32 "
                 "{%0,%1,%2,%3}, {%4,%5,%6,%7}, {%8,%9}, {%0,%1,%2,%3};"
                 : "+f"(c[0]), "+f"(c[1]), "+f"(c[2]), "+f"(c[3])
                 : "r"(a0), "r"(a1), "r"(a2), "r"(a3), "r"(b0), "r"(b1));
}
__device__ __forceinline__ uint32_t packbf(float a, float b) {
    __nv_bfloat162 h = __floats2bfloat162_rn(a, b);
    return *reinterpret_cast<uint32_t*>(&h);
}

// ---------------------------------------------------------------------------
// Weight pre-convert fp32 -> bf16
// ---------------------------------------------------------------------------
__global__ void wconv(const float* __restrict__ a, const float* __restrict__ b,
                      const float* __restrict__ c, const float* __restrict__ d,
                      __nv_bfloat16* __restrict__ o) {
    int i = blockIdx.x * 256 + threadIdx.x;
    if (i < 27648)       o[i] = __float2bfloat16(a[i]);
    else if (i < 36864)  o[i] = __float2bfloat16(b[i - 27648]);
    else if (i < 73728)  o[i] = __float2bfloat16(c[i - 36864]);
    else if (i < 110592) o[i] = __float2bfloat16(d[i - 73728]);
}

// ---------------------------------------------------------------------------
// Combined bias table: tab[cls][h][i(64)][j(64)] = rpb + shiftmask, pad -> -1e30
// cls = (wh==7)*2 + (ww==7)
// ---------------------------------------------------------------------------
__device__ __forceinline__ int winlab(int cls, int r, int c) {
    int rh = (cls & 2) ? (r < 4 ? 1 : 2) : 0;
    int rw = (cls & 1) ? (c < 4 ? 1 : 2) : 0;
    return rh * 3 + rw;
}
__global__ void bias_prep(const float* __restrict__ rpb, __nv_bfloat16* __restrict__ tab) {
    int idx = blockIdx.x * 256 + threadIdx.x;
    if (idx >= 4 * 3 * 64 * 64) return;
    int j = idx & 63, i = (idx >> 6) & 63;
    int h = (idx >> 12) % 3, cls = idx >> 12; cls /= 3;
    float v;
    if (j >= 49 || i >= 49) v = -1e30f;
    else {
        int ri = i / 7, ci = i % 7, rj = j / 7, cj = j % 7;
        v = rpb[((ri - rj + 6) * 13 + (ci - cj + 6)) * 3 + h];
        if (winlab(cls, ri, ci) != winlab(cls, rj, cj)) v -= 100.0f;
    }
    tab[idx] = __float2bfloat16(v);
}

// ---------------------------------------------------------------------------
// LN kernel (one warp per token, bf16 out, shift+partition gather)
// ---------------------------------------------------------------------------
__global__ void ln_kernel(const float* __restrict__ x, const float* __restrict__ g,
                          const float* __restrict__ b, __nv_bfloat16* __restrict__ out,
                          int shifted) {
    int warp = (blockIdx.x * blockDim.x + threadIdx.x) >> 5;
    int lane = threadIdx.x & 31;
    if (warp >= TKN) return;
    int src = warp;
    if (shifted) {
        int bi  = warp / 3136;
        int rem = warp % 3136;
        int w   = rem / 49, n = rem % 49;
        int wh = w >> 3, ww = w & 7;
        int r = n / 7, cc = n % 7;
        int sh = wh * 7 + r + 3;  if (sh >= 56) sh -= 56;
        int sw = ww * 7 + cc + 3; if (sw >= 56) sw -= 56;
        src = bi * 3136 + sh * 56 + sw;
    }
    const float* xr = x + (size_t)src * 96;
    float v0 = xr[lane], v1 = xr[lane + 32], v2 = xr[lane + 64];
    float s  = v0 + v1 + v2;
    float s2 = v0 * v0 + v1 * v1 + v2 * v2;
    #pragma unroll
    for (int o = 16; o; o >>= 1) {
        s  += __shfl_xor_sync(0xffffffffu, s,  o);
        s2 += __shfl_xor_sync(0xffffffffu, s2, o);
    }
    float mean = s * (1.0f / 96.0f);
    float var  = s2 * (1.0f / 96.0f) - mean * mean;
    float rs   = rsqrtf(var + 1e-5f);
    __nv_bfloat16* orow = out + (size_t)warp * 96;
    orow[lane]      = __float2bfloat16((v0 - mean) * rs * g[lane]      + b[lane]);
    orow[lane + 32] = __float2bfloat16((v1 - mean) * rs * g[lane + 32] + b[lane + 32]);
    orow[lane + 64] = __float2bfloat16((v2 - mean) * rs * g[lane + 64] + b[lane + 64]);
}

// ---------------------------------------------------------------------------
// Pipelined HMMA GEMM. MODE 1 additionally fuses LN2: writes fp32 residual
// stream to d_out AND the layernormed bf16 row to ln2out (distinct buffer!).
// ---------------------------------------------------------------------------
template <int MODE, int KGLOB, int KCH, int NOUT, int TILES>
__global__ void __launch_bounds__(256, 2)
tc_gemm(const __nv_bfloat16* __restrict__ A, const __nv_bfloat16* __restrict__ Wb,
        const float* __restrict__ bias, void* __restrict__ outv,
        const float* __restrict__ resid, const float* __restrict__ g2,
        const float* __restrict__ b2, __nv_bfloat16* __restrict__ ln2out) {
    constexpr bool BRES = (KCH == 1);
    constexpr int ABYTES = 128 * 104 * 2;
    constexpr int BBYTES = 96 * 104 * 2;
    constexpr int PART_OFF = 2 * ABYTES + BBYTES;   // MODE1 LN partials
    extern __shared__ char smem[];
    const uint32_t sbase = smem_u32(smem);
    const uint32_t Ab0 = sbase, Ab1 = sbase + ABYTES;
    const uint32_t Bb0 = sbase + 2 * ABYTES;
    const uint32_t Bb1 = BRES ? Bb0 : Bb0 + BBYTES;

    const int tid   = threadIdx.x;
    const int lane  = tid & 31;
    const int wid   = tid >> 5;
    const int wm    = wid & 3;
    const int wn    = wid >> 2;
    const int nb    = blockIdx.y;
    const int tile0 = blockIdx.x * TILES;
    const int NSTEP = TILES * KCH;

    auto issueA = [&](int s) {
        int tile = s / KCH, kc = s % KCH;
        const __nv_bfloat16* src = A + (size_t)(tile0 + tile) * 128 * KGLOB + kc * 96;
        uint32_t dst = (s & 1) ? Ab1 : Ab0;
        #pragma unroll
        for (int i = tid; i < 128 * 24; i += 256) {
            int r = i / 24, c = i % 24;
            cp8(dst + r * 208 + c * 8, src + (size_t)r * KGLOB + c * 4);
        }
    };
    auto issueB = [&](int s) {
        int kc = s % KCH;
        const __nv_bfloat16* src = Wb + (size_t)nb * 96 * KGLOB + kc * 96;
        uint32_t dst = (s & 1) ? Bb1 : Bb0;
        #pragma unroll
        for (int i = tid; i < 96 * 24; i += 256) {
            int r = i / 24, c = i % 24;
            cp8(dst + r * 208 + c * 8, src + (size_t)r * KGLOB + c * 4);
        }
    };

    issueA(0); issueB(0); CP_COMMIT();

    float acc[2][6][4];

    for (int s = 0; s < NSTEP; s++) {
        const int kc = s % KCH, tile = s / KCH;
        const bool hasnext = (s + 1 < NSTEP);
        if (hasnext) {
            issueA(s + 1);
            if (!BRES) issueB(s + 1);
            CP_COMMIT();
            asm volatile("cp.async.wait_group 1;" ::: "memory");
        } else {
            asm volatile("cp.async.wait_group 0;" ::: "memory");
        }
        __syncthreads();

        if (kc == 0) {
            #pragma unroll
            for (int m = 0; m < 2; m++)
                #pragma unroll
                for (int n = 0; n < 6; n++)
                    #pragma unroll
                    for (int v = 0; v < 4; v++) acc[m][n][v] = 0.0f;
        }

        const uint32_t abase = (s & 1) ? Ab1 : Ab0;
        const uint32_t bbase = BRES ? Bb0 : ((s & 1) ? Bb1 : Bb0);

        #pragma unroll
        for (int kk = 0; kk < 6; kk++) {
            const int k = kk * 16;
            uint32_t a[2][4];
            #pragma unroll
            for (int m = 0; m < 2; m++)
                ldm_x4(a[m][0], a[m][1], a[m][2], a[m][3],
                       abase + ((uint32_t)((wm * 32 + m * 16 + (lane & 15)) * 104
                                           + k + (lane >> 4) * 8) << 1));
            #pragma unroll
            for (int g = 0; g < 3; g++) {
                uint32_t b0, b1, b2, b3;
                ldm_x4(b0, b1, b2, b3,
                       bbase + ((uint32_t)((wn * 48 + g * 16 + (lane & 15)) * 104
                                           + k + (lane >> 4) * 8) << 1));
                #pragma unroll
                for (int m = 0; m < 2; m++) {
                    mma_bf16(acc[m][g * 2],     a[m][0], a[m][1], a[m][2], a[m][3], b0, b2);
                    mma_bf16(acc[m][g * 2 + 1], a[m][0], a[m][1], a[m][2], a[m][3], b1, b3);
                }
            }
        }

        if (kc == KCH - 1) {
            const int row0 = (tile0 + tile) * 128 + wm * 32;
            const int colb = nb * 96 + wn * 48;
            if (MODE == 1) {
                // fused: residual add + d_out write + LN2 -> ln2out (bf16)
                float* part = reinterpret_cast<float*>(smem + PART_OFF);
                int dda[2], ddb[2];
                #pragma unroll
                for (int m = 0; m < 2; m++) {
                    const int ra = row0 + m * 16 + (lane >> 2);
                    const int rb = ra + 8;
                    #pragma unroll
                    for (int t2 = 0; t2 < 2; t2++) {
                        int row = t2 ? rb : ra;
                        int bi  = row / 3136;
                        int rem = row % 3136;
                        int ww_ = rem / 49, n = rem % 49;
                        int wh = ww_ >> 3, wcl = ww_ & 7;
                        int r7 = n / 7, c7 = n % 7;
                        int hh = wh * 7 + r7 + 3;  if (hh >= 56) hh -= 56;
                        int zz = wcl * 7 + c7 + 3; if (zz >= 56) zz -= 56;
                        int d = bi * 3136 + hh * 56 + zz;
                        if (t2) ddb[m] = d; else dda[m] = d;
                    }
                    float sa = 0.f, qa = 0.f, sb = 0.f, qb = 0.f;
                    #pragma unroll
                    for (int n = 0; n < 6; n++) {
                        const int col = colb + n * 8 + (lane & 3) * 2;
                        float bi0 = __ldg(bias + col), bi1 = __ldg(bias + col + 1);
                        float w00 = acc[m][n][0] + bi0, w01 = acc[m][n][1] + bi1;
                        float w10 = acc[m][n][2] + bi0, w11 = acc[m][n][3] + bi1;
                        size_t oa = (size_t)dda[m] * 96 + col, ob = (size_t)ddb[m] * 96 + col;
                        float2 r0 = *reinterpret_cast<const float2*>(resid + oa);
                        float2 r1 = *reinterpret_cast<const float2*>(resid + ob);
                        w00 += r0.x; w01 += r0.y; w10 += r1.x; w11 += r1.y;
                        *reinterpret_cast<float2*>((float*)outv + oa) = make_float2(w00, w01);
                        *reinterpret_cast<float2*>((float*)outv + ob) = make_float2(w10, w11);
                        acc[m][n][0] = w00; acc[m][n][1] = w01;
                        acc[m][n][2] = w10; acc[m][n][3] = w11;
                        sa += w00 + w01; qa += w00 * w00 + w01 * w01;
                        sb += w10 + w11; qb += w10 * w10 + w11 * w11;
                    }
                    sa += __shfl_xor_sync(0xffffffffu, sa, 1); sa += __shfl_xor_sync(0xffffffffu, sa, 2);
                    qa += __shfl_xor_sync(0xffffffffu, qa, 1); qa += __shfl_xor_sync(0xffffffffu, qa, 2);
                    sb += __shfl_xor_sync(0xffffffffu, sb, 1); sb += __shfl_xor_sync(0xffffffffu, sb, 2);
                    qb += __shfl_xor_sync(0xffffffffu, qb, 1); qb += __shfl_xor_sync(0xffffffffu, qb, 2);
                    if ((lane & 3) == 0) {
                        int lra = wm * 32 + m * 16 + (lane >> 2);
                        part[(wn * 128 + lra) * 2]         = sa;
                        part[(wn * 128 + lra) * 2 + 1]     = qa;
                        part[(wn * 128 + lra + 8) * 2]     = sb;
                        part[(wn * 128 + lra + 8) * 2 + 1] = qb;
                    }
                }
                __syncthreads();
                #pragma unroll
                for (int m = 0; m < 2; m++) {
                    int lra = wm * 32 + m * 16 + (lane >> 2);
                    float sA = part[lra * 2] + part[(128 + lra) * 2];
                    float qA = part[lra * 2 + 1] + part[(128 + lra) * 2 + 1];
                    float sB = part[(lra + 8) * 2] + part[(128 + lra + 8) * 2];
                    float qB = part[(lra + 8) * 2 + 1] + part[(128 + lra + 8) * 2 + 1];
                    float mA = sA * (1.0f / 96.0f);
                    float rA = rsqrtf(qA * (1.0f / 96.0f) - mA * mA + 1e-5f);
                    float mB = sB * (1.0f / 96.0f);
                    float rB = rsqrtf(qB * (1.0f / 96.0f) - mB * mB + 1e-5f);
                    #pragma unroll
                    for (int n = 0; n < 6; n++) {
                        const int col = colb + n * 8 + (lane & 3) * 2;
                        float g0 = __ldg(g2 + col), g1 = __ldg(g2 + col + 1);
                        float c0 = __ldg(b2 + col), c1 = __ldg(b2 + col + 1);
                        float l00 = (acc[m][n][0] - mA) * rA * g0 + c0;
                        float l01 = (acc[m][n][1] - mA) * rA * g1 + c1;
                        float l10 = (acc[m][n][2] - mB) * rB * g0 + c0;
                        float l11 = (acc[m][n][3] - mB) * rB * g1 + c1;
                        *reinterpret_cast<uint32_t*>(ln2out + (size_t)dda[m] * 96 + col) = packbf(l00, l01);
                        *reinterpret_cast<uint32_t*>(ln2out + (size_t)ddb[m] * 96 + col) = packbf(l10, l11);
                    }
                }
            } else {
                #pragma unroll
                for (int m = 0; m < 2; m++) {
                    const int ra = row0 + m * 16 + (lane >> 2);
                    const int rb = ra + 8;
                    #pragma unroll
                    for (int n = 0; n < 6; n++) {
                        const int col = colb + n * 8 + (lane & 3) * 2;
                        float bi0 = __ldg(bias + col), bi1 = __ldg(bias + col + 1);
                        float v00 = acc[m][n][0] + bi0, v01 = acc[m][n][1] + bi1;
                        float v10 = acc[m][n][2] + bi0, v11 = acc[m][n][3] + bi1;
                        if (MODE == 0) {
                            if (col < 96) { v00 *= QSCALE; v01 *= QSCALE; v10 *= QSCALE; v11 *= QSCALE; }
                            __nv_bfloat16* out = (__nv_bfloat16*)outv;
                            *reinterpret_cast<uint32_t*>(out + (size_t)ra * NOUT + col) = packbf(v00, v01);
                            *reinterpret_cast<uint32_t*>(out + (size_t)rb * NOUT + col) = packbf(v10, v11);
                        } else if (MODE == 2) {
                            v00 = 0.5f * v00 * (1.0f + erff(v00 * 0.70710678118654752f));
                            v01 = 0.5f * v01 * (1.0f + erff(v01 * 0.70710678118654752f));
                            v10 = 0.5f * v10 * (1.0f + erff(v10 * 0.70710678118654752f));
                            v11 = 0.5f * v11 * (1.0f + erff(v11 * 0.70710678118654752f));
                            __nv_bfloat16* out = (__nv_bfloat16*)outv;
                            *reinterpret_cast<uint32_t*>(out + (size_t)ra * NOUT + col) = packbf(v00, v01);
                            *reinterpret_cast<uint32_t*>(out + (size_t)rb * NOUT + col) = packbf(v10, v11);
                        } else {
                            float* out = (float*)outv;
                            size_t oa = (size_t)ra * 96 + col, ob = (size_t)rb * 96 + col;
                            float2 r0 = *reinterpret_cast<const float2*>(out + oa);
                            float2 r1 = *reinterpret_cast<const float2*>(out + ob);
                            r0.x += v00; r0.y += v01; r1.x += v10; r1.y += v11;
                            *reinterpret_cast<float2*>(out + oa) = r0;
                            *reinterpret_cast<float2*>(out + ob) = r1;
                        }
                    }
                }
            }
        }
        __syncthreads();
    }
}

// ---------------------------------------------------------------------------
// Tensor-core windowed attention (bias table version, m-tiles serialized)
// ---------------------------------------------------------------------------
__global__ void __launch_bounds__(192, 3)
attn_tc(const __nv_bfloat16* __restrict__ qkv, const __nv_bfloat16* __restrict__ btab,
        __nv_bfloat16* __restrict__ out) {
    extern __shared__ char ash[];
    __nv_bfloat16* Qs = reinterpret_cast<__nv_bfloat16*>(ash);
    __nv_bfloat16* Ks = Qs + 7680;
    __nv_bfloat16* Vs = Ks + 7680;

    const uint32_t qb = smem_u32(Qs), kb = smem_u32(Ks), vb = smem_u32(Vs);
    const int wb  = blockIdx.x;
    const int t0  = wb * 49;
    const int tid = threadIdx.x;
    const int lane = tid & 31;
    const int wid  = tid >> 5;

    for (int idx = tid; idx < 64 * 144; idx += 192) {
        int j = idx / 144, w = idx % 144;
        int arr = w / 48, ww = w % 48;
        int h = ww / 16, d2 = ww % 16;
        uint32_t val = 0;
        if (j < 49)
            val = reinterpret_cast<const uint32_t*>(qkv + (size_t)(t0 + j) * 288)[w];
        uint32_t off = (uint32_t)(h * 2560 + j * 40 + d2 * 2);
        __nv_bfloat16* base = (arr == 0) ? Qs : (arr == 1) ? Ks : Vs;
        *reinterpret_cast<uint32_t*>(base + off) = val;
    }
    __syncthreads();

    const int h  = wid >> 1;
    const int mh = wid & 1;
    const uint32_t qh = qb + (uint32_t)h * 5120;
    const uint32_t kh = kb + (uint32_t)h * 5120;
    const uint32_t vh = vb + (uint32_t)h * 5120;

    const int w_   = wb & 63;
    const int cls  = ((w_ >> 3) == 7 ? 2 : 0) | ((w_ & 7) == 7 ? 1 : 0);
    const __nv_bfloat16* bt = btab + ((size_t)(cls * 3 + h) << 12);

    #pragma unroll
    for (int mt = 0; mt < 2; mt++) {
        const int rbase = mh * 32 + mt * 16;

        float c[8][4];
        #pragma unroll
        for (int n = 0; n < 8; n++)
            #pragma unroll
            for (int v = 0; v < 4; v++) c[n][v] = 0.0f;

        #pragma unroll
        for (int kk = 0; kk < 2; kk++) {
            uint32_t qa0, qa1, qa2, qa3;
            ldm_x4(qa0, qa1, qa2, qa3,
                   qh + ((uint32_t)((rbase + (lane & 15)) * 40 + kk * 16 + (lane >> 4) * 8) << 1));
            #pragma unroll
            for (int np = 0; np < 4; np++) {
                uint32_t b0, b1, b2, b3;
                ldm_x4(b0, b1, b2, b3,
                       kh + ((uint32_t)((np * 16 + (lane & 15)) * 40 + kk * 16 + (lane >> 4) * 8) << 1));
                mma_bf16(c[np * 2],     qa0, qa1, qa2, qa3, b0, b2);
                mma_bf16(c[np * 2 + 1], qa0, qa1, qa2, qa3, b1, b3);
            }
        }

        const int i0 = rbase + (lane >> 2);
        const uint32_t* br0 = reinterpret_cast<const uint32_t*>(bt + i0 * 64) + (lane & 3);
        const uint32_t* br1 = reinterpret_cast<const uint32_t*>(bt + (i0 + 8) * 64) + (lane & 3);
        #pragma unroll
        for (int nt = 0; nt < 8; nt++) {
            uint32_t w0 = __ldg(br0 + nt * 4);
            uint32_t w1 = __ldg(br1 + nt * 4);
            float2 f0 = __bfloat1622float2(*reinterpret_cast<__nv_bfloat162*>(&w0));
            float2 f1 = __bfloat1622float2(*reinterpret_cast<__nv_bfloat162*>(&w1));
            c[nt][0] += f0.x; c[nt][1] += f0.y;
            c[nt][2] += f1.x; c[nt][3] += f1.y;
        }

        #pragma unroll
        for (int p = 0; p < 2; p++) {
            float mx = -1e30f;
            #pragma unroll
            for (int nt = 0; nt < 8; nt++) {
                mx = fmaxf(mx, c[nt][p * 2]);
                mx = fmaxf(mx, c[nt][p * 2 + 1]);
            }
            mx = fmaxf(mx, __shfl_xor_sync(0xffffffffu, mx, 1));
            mx = fmaxf(mx, __shfl_xor_sync(0xffffffffu, mx, 2));
            float sum = 0.0f;
            #pragma unroll
            for (int nt = 0; nt < 8; nt++) {
                float e0 = __expf(c[nt][p * 2]     - mx);
                float e1 = __expf(c[nt][p * 2 + 1] - mx);
                c[nt][p * 2] = e0; c[nt][p * 2 + 1] = e1;
                sum += e0 + e1;
            }
            sum += __shfl_xor_sync(0xffffffffu, sum, 1);
            sum += __shfl_xor_sync(0xffffffffu, sum, 2);
            float inv = 1.0f / sum;
            #pragma unroll
            for (int nt = 0; nt < 8; nt++) {
                c[nt][p * 2] *= inv; c[nt][p * 2 + 1] *= inv;
            }
        }

        float o[4][4];
        #pragma unroll
        for (int n = 0; n < 4; n++)
            #pragma unroll
            for (int v = 0; v < 4; v++) o[n][v] = 0.0f;

        #pragma unroll
        for (int kk = 0; kk < 4; kk++) {
            uint32_t vf[2][4];
            #pragma unroll
            for (int dh = 0; dh < 2; dh++)
                ldm_x4t(vf[dh][0], vf[dh][1], vf[dh][2], vf[dh][3],
                        vh + ((uint32_t)((kk * 16 + (lane & 7) + ((lane >> 3) & 1) * 8) * 40
                                         + dh * 16 + (lane >> 4) * 8) << 1));
            uint32_t pa0 = packbf(c[2 * kk][0],     c[2 * kk][1]);
            uint32_t pa1 = packbf(c[2 * kk][2],     c[2 * kk][3]);
            uint32_t pa2 = packbf(c[2 * kk + 1][0], c[2 * kk + 1][1]);
            uint32_t pa3 = packbf(c[2 * kk + 1][2], c[2 * kk + 1][3]);
            #pragma unroll
            for (int dn = 0; dn < 4; dn++) {
                uint32_t vb0 = (dn & 1) ? vf[dn >> 1][2] : vf[dn >> 1][0];
                uint32_t vb1 = (dn & 1) ? vf[dn >> 1][3] : vf[dn >> 1][1];
                mma_bf16(o[dn], pa0, pa1, pa2, pa3, vb0, vb1);
            }
        }

        #pragma unroll
        for (int p = 0; p < 2; p++) {
            int i = rbase + (lane >> 2) + p * 8;
            if (i < 49) {
                __nv_bfloat16* orow = out + (size_t)(t0 + i) * 96 + h * 32;
                #pragma unroll
                for (int dn = 0; dn < 4; dn++) {
                    int d = dn * 8 + (lane & 3) * 2;
                    *reinterpret_cast<uint32_t*>(orow + d) = packbf(o[dn][p * 2], o[dn][p * 2 + 1]);
                }
            }
        }
    }
}

// ---------------------------------------------------------------------------
extern "C" void kernel_launch(void* const* d_in, const int* in_sizes, int n_in,
                              void* d_out, int out_size) {
    const float* x      = (const float*)d_in[0];
    const float* n1g    = (const float*)d_in[1];
    const float* n1b    = (const float*)d_in[2];
    const float* qkv_w  = (const float*)d_in[3];
    const float* qkv_b  = (const float*)d_in[4];
    const float* rpb    = (const float*)d_in[5];
    const float* proj_w = (const float*)d_in[6];
    const float* proj_b = (const float*)d_in[7];
    const float* n2g    = (const float*)d_in[8];
    const float* n2b    = (const float*)d_in[9];
    const float* fc1_w  = (const float*)d_in[10];
    const float* fc1_b  = (const float*)d_in[11];
    const float* fc2_w  = (const float*)d_in[12];
    const float* fc2_b  = (const float*)d_in[13];
    float* out = (float*)d_out;

    __nv_bfloat16 *buf1, *buf2, *buf3, *wb, *bt;
    cudaGetSymbolAddress((void**)&buf1, g_buf1);
    cudaGetSymbolAddress((void**)&buf2, g_buf2);
    cudaGetSymbolAddress((void**)&buf3, g_buf3);
    cudaGetSymbolAddress((void**)&wb,   g_wbuf);
    cudaGetSymbolAddress((void**)&bt,   g_bias);

    const int smem_k96   = 2 * 26624 + 19968;            // 73216
    const int smem_proj  = 2 * 26624 + 19968 + 2048;     // + LN partials
    const int smem_k384  = 2 * 26624 + 2 * 19968;
    const int smem_attn  = 3 * 7680 * 2;                 // 46080
    cudaFuncSetAttribute(tc_gemm<0, 96, 1, 288, 8>,   cudaFuncAttributeMaxDynamicSharedMemorySize, smem_k96);
    cudaFuncSetAttribute(tc_gemm<1, 96, 1, 96, 4>,    cudaFuncAttributeMaxDynamicSharedMemorySize, smem_proj);
    cudaFuncSetAttribute(tc_gemm<2, 96, 1, 384, 16>,  cudaFuncAttributeMaxDynamicSharedMemorySize, smem_k96);
    cudaFuncSetAttribute(tc_gemm<3, 384, 4, 96, 4>,   cudaFuncAttributeMaxDynamicSharedMemorySize, smem_k384);
    cudaFuncSetAttribute(attn_tc, cudaFuncAttributeMaxDynamicSharedMemorySize, smem_attn);

    // 0) weights fp32 -> bf16; combined bias table
    wconv<<<432, 256>>>(qkv_w, proj_w, fc1_w, fc2_w, wb);
    bias_prep<<<192, 256>>>(rpb, bt);
    // 1) LN1 + shift + window partition -> buf2 bf16 [T,96]
    ln_kernel<<<TKN / 8, 256>>>(x, n1g, n1b, buf2, 1);
    // 2) QKV GEMM (q pre-scaled) -> buf1 bf16 [T,288]
    tc_gemm<0, 96, 1, 288, 8><<<dim3(196, 3), 256, smem_k96>>>(buf2, wb + WOFF_QKV, qkv_b, buf1, nullptr, nullptr, nullptr, nullptr);
    // 3) tensor-core windowed attention -> buf2 bf16 [T,96]
    attn_tc<<<4096, 192, smem_attn>>>(buf1, bt, buf2);
    // 4) proj GEMM + window reverse + unshift + residual + fused LN2
    //    -> d_out fp32 [T,96], buf3 bf16 LN2 [T,96]   (NO aliasing with input buf2)
    tc_gemm<1, 96, 1, 96, 4><<<dim3(392, 1), 256, smem_proj>>>(buf2, wb + WOFF_PROJ, proj_b, out, x, n2g, n2b, buf3);
    // 5) FC1 + GELU -> buf1 bf16 [T,384]
    tc_gemm<2, 96, 1, 384, 16><<<dim3(98, 4), 256, smem_k96>>>(buf3, wb + WOFF_FC1, fc1_b, buf1, nullptr, nullptr, nullptr, nullptr);
    // 6) FC2 + accumulate into d_out
    tc_gemm<3, 384, 4, 96, 4><<<dim3(392, 1), 256, smem_k384>>>(buf1, wb + WOFF_FC2, fc2_b, out, nullptr, nullptr, nullptr, nullptr);
}